// round 1
// baseline (speedup 1.0000x reference)
#include <cuda_runtime.h>

#define NN   50000
#define NE   1600000
#define NG   512
#define IND  64
#define HID  128
#define OUTD 10

// ---------------- scratch (static __device__ — no allocation) ----------------
__device__ int   g_is64;
__device__ int   g_src[NE];
__device__ int   g_dst[NE];
__device__ int   g_batch[NN];
__device__ float g_deg[NN];
__device__ float g_dinv[NN];
__device__ int   g_count[NN];
__device__ int   g_rowptr[NN + 1];
__device__ int   g_cursor[NN];
__device__ int   g_esrc[NE];
__device__ float g_enorm[NE];
__device__ float g_h1[NN * HID];
__device__ float g_a1[NN * HID];
__device__ float g_h2[NN * HID];
__device__ float g_a2[NN * HID];
__device__ float g_pool[NG * HID];

// ---------------- dtype detection: int64 vs int32 indices ----------------
__global__ void k_detect(const unsigned* __restrict__ w) {
    if (threadIdx.x == 0 && blockIdx.x == 0) {
        int is64 = 1;
        #pragma unroll 1
        for (int i = 0; i < 128; i++) {
            if (w[2 * i + 1] != 0u) { is64 = 0; break; }
        }
        g_is64 = is64;
    }
}

// normalize edge_index + batch into int32 arrays; init deg/count/pool
__global__ void k_convert(const void* __restrict__ ei, const void* __restrict__ batch) {
    int i = blockIdx.x * blockDim.x + threadIdx.x;
    int is64 = g_is64;
    if (is64) {
        const long long* p = (const long long*)ei;
        if (i < NE) { g_src[i] = (int)p[i]; g_dst[i] = (int)p[NE + i]; }
        if (i < NN) g_batch[i] = (int)((const long long*)batch)[i];
    } else {
        const int* p = (const int*)ei;
        if (i < NE) { g_src[i] = p[i]; g_dst[i] = p[NE + i]; }
        if (i < NN) g_batch[i] = ((const int*)batch)[i];
    }
    if (i < NN) { g_deg[i] = 1.0f; g_count[i] = 0; }   // self-loop weight 1
    if (i < NG * HID) g_pool[i] = 0.0f;
}

// ---------------- degree + in-degree histogram ----------------
__global__ void k_deg(const float* __restrict__ ew) {
    int e = blockIdx.x * blockDim.x + threadIdx.x;
    if (e >= NE) return;
    int d = g_dst[e];
    atomicAdd(&g_deg[d], ew[e]);
    atomicAdd(&g_count[d], 1);
}

__global__ void k_dinv() {
    int i = blockIdx.x * blockDim.x + threadIdx.x;
    if (i < NN) g_dinv[i] = rsqrtf(g_deg[i]);   // deg >= 1 always (self-loop)
}

// ---------------- exclusive scan of in-degrees -> CSR row_ptr ----------------
__global__ void k_scan() {
    __shared__ int s[1024];
    __shared__ int carry_s;
    int tid = threadIdx.x;
    if (tid == 0) carry_s = 0;
    __syncthreads();
    for (int base = 0; base < NN; base += 1024) {
        int idx = base + tid;
        int v = (idx < NN) ? g_count[idx] : 0;
        s[tid] = v;
        __syncthreads();
        #pragma unroll
        for (int off = 1; off < 1024; off <<= 1) {
            int t = (tid >= off) ? s[tid - off] : 0;
            __syncthreads();
            s[tid] += t;
            __syncthreads();
        }
        int excl = carry_s + s[tid] - v;
        if (idx < NN) { g_rowptr[idx] = excl; g_cursor[idx] = excl; }
        __syncthreads();
        if (tid == 0) carry_s += s[1023];
        __syncthreads();
    }
    if (tid == 0) g_rowptr[NN] = NE;
}

// ---------------- scatter edges into CSR buckets with precomputed norm ----------------
__global__ void k_scatter(const float* __restrict__ ew) {
    int e = blockIdx.x * blockDim.x + threadIdx.x;
    if (e >= NE) return;
    int s = g_src[e];
    int d = g_dst[e];
    float nrm = g_dinv[s] * ew[e] * g_dinv[d];
    int pos = atomicAdd(&g_cursor[d], 1);
    g_esrc[pos] = s;
    g_enorm[pos] = nrm;
}

// ---------------- GEMM: h1 = x @ W1   (50000 x 64 @ 64 x 128) ----------------
__global__ void __launch_bounds__(256) k_gemm_in(const float* __restrict__ x,
                                                 const float* __restrict__ W) {
    __shared__ float Ws[IND * HID];   // 32 KB
    __shared__ float xs[32 * IND];    //  8 KB
    int tid = threadIdx.x;
    int row0 = blockIdx.x * 32;
    for (int i = tid; i < IND * HID / 4; i += 256)
        ((float4*)Ws)[i] = ((const float4*)W)[i];
    for (int i = tid; i < 32 * IND / 4; i += 256) {
        int row = row0 + i / (IND / 4);
        float4 v = make_float4(0.f, 0.f, 0.f, 0.f);
        if (row < NN) v = ((const float4*)x)[row * (IND / 4) + (i % (IND / 4))];
        ((float4*)xs)[i] = v;
    }
    __syncthreads();
    int warp = tid >> 5, lane = tid & 31;
    int rbase = warp * 4;
    float4 acc[4];
    #pragma unroll
    for (int r = 0; r < 4; r++) acc[r] = make_float4(0.f, 0.f, 0.f, 0.f);
    #pragma unroll 4
    for (int k = 0; k < IND; k++) {
        float4 w = ((float4*)Ws)[k * 32 + lane];
        #pragma unroll
        for (int r = 0; r < 4; r++) {
            float xv = xs[(rbase + r) * IND + k];
            acc[r].x += xv * w.x; acc[r].y += xv * w.y;
            acc[r].z += xv * w.z; acc[r].w += xv * w.w;
        }
    }
    #pragma unroll
    for (int r = 0; r < 4; r++) {
        int row = row0 + rbase + r;
        if (row < NN) ((float4*)g_h1)[row * 32 + lane] = acc[r];
    }
}

// ---------------- GEMM: h2 = a1 @ W2   (50000 x 128 @ 128 x 128) ----------------
__global__ void __launch_bounds__(256) k_gemm_hid(const float* __restrict__ W) {
    __shared__ float Ws[64 * HID];    // 32 KB (one K-chunk of W2)
    __shared__ float xs[32 * HID];    // 16 KB
    int tid = threadIdx.x;
    int row0 = blockIdx.x * 32;
    for (int i = tid; i < 32 * HID / 4; i += 256) {
        int row = row0 + i / (HID / 4);
        float4 v = make_float4(0.f, 0.f, 0.f, 0.f);
        if (row < NN) v = ((const float4*)g_a1)[row * (HID / 4) + (i % (HID / 4))];
        ((float4*)xs)[i] = v;
    }
    int warp = tid >> 5, lane = tid & 31;
    int rbase = warp * 4;
    float4 acc[4];
    #pragma unroll
    for (int r = 0; r < 4; r++) acc[r] = make_float4(0.f, 0.f, 0.f, 0.f);
    for (int c = 0; c < 2; c++) {
        __syncthreads();
        for (int i = tid; i < 64 * HID / 4; i += 256)
            ((float4*)Ws)[i] = ((const float4*)(W + c * 64 * HID))[i];
        __syncthreads();
        #pragma unroll 4
        for (int k = 0; k < 64; k++) {
            int kk = c * 64 + k;
            float4 w = ((float4*)Ws)[k * 32 + lane];
            #pragma unroll
            for (int r = 0; r < 4; r++) {
                float xv = xs[(rbase + r) * HID + kk];
                acc[r].x += xv * w.x; acc[r].y += xv * w.y;
                acc[r].z += xv * w.z; acc[r].w += xv * w.w;
            }
        }
    }
    #pragma unroll
    for (int r = 0; r < 4; r++) {
        int row = row0 + rbase + r;
        if (row < NN) ((float4*)g_h2)[row * 32 + lane] = acc[r];
    }
}

// ---------------- aggregation: out = relu(scatter(norm * h[src]) + self + b) ----------------
// one warp per node; lanes hold a float4 slice of the 128-wide feature.
__global__ void __launch_bounds__(256) k_agg(const float* __restrict__ bias, int phase) {
    int node = (blockIdx.x * 256 + threadIdx.x) >> 5;
    int lane = threadIdx.x & 31;
    if (node >= NN) return;
    const float4* h = (const float4*)(phase ? g_h2 : g_h1);
    float4* out     = (float4*)(phase ? g_a2 : g_a1);
    float d = g_dinv[node];
    float sl = d * d;                           // self-loop norm (ew=1)
    float4 acc = h[node * 32 + lane];
    acc.x *= sl; acc.y *= sl; acc.z *= sl; acc.w *= sl;
    int e   = g_rowptr[node];
    int end = g_rowptr[node + 1];
    #pragma unroll 2
    for (; e < end; e++) {
        int s    = __ldg(&g_esrc[e]);           // warp-uniform broadcast
        float nm = __ldg(&g_enorm[e]);
        float4 hs = h[s * 32 + lane];           // random gather — L2 resident
        acc.x += hs.x * nm; acc.y += hs.y * nm;
        acc.z += hs.z * nm; acc.w += hs.w * nm;
    }
    float4 b = ((const float4*)bias)[lane];
    acc.x = fmaxf(acc.x + b.x, 0.f);
    acc.y = fmaxf(acc.y + b.y, 0.f);
    acc.z = fmaxf(acc.z + b.z, 0.f);
    acc.w = fmaxf(acc.w + b.w, 0.f);
    out[node * 32 + lane] = acc;
}

// ---------------- global add pool ----------------
__global__ void __launch_bounds__(256) k_pool() {
    int t = blockIdx.x * blockDim.x + threadIdx.x;
    int node = t >> 5;
    if (node >= NN) return;
    int lane = t & 31;
    float4 v = ((const float4*)g_a2)[node * 32 + lane];
    int g = g_batch[node];
    float* p = &g_pool[g * HID + lane * 4];
    atomicAdd(p + 0, v.x);
    atomicAdd(p + 1, v.y);
    atomicAdd(p + 2, v.z);
    atomicAdd(p + 3, v.w);
}

// ---------------- MLP head: out = relu(pool @ Wm1 + bm1) @ Wm2 + bm2 ----------------
__global__ void __launch_bounds__(128) k_mlp(const float* __restrict__ Wm1,
                                             const float* __restrict__ bm1,
                                             const float* __restrict__ Wm2,
                                             const float* __restrict__ bm2,
                                             float* __restrict__ out) {
    int g = blockIdx.x;
    int tid = threadIdx.x;
    __shared__ float ps[HID];
    __shared__ float zs[HID];
    ps[tid] = g_pool[g * HID + tid];
    __syncthreads();
    float acc = bm1[tid];
    #pragma unroll 8
    for (int k = 0; k < HID; k++) acc += ps[k] * Wm1[k * HID + tid];
    zs[tid] = fmaxf(acc, 0.f);
    __syncthreads();
    if (tid < OUTD) {
        float a = bm2[tid];
        #pragma unroll 8
        for (int k = 0; k < HID; k++) a += zs[k] * Wm2[k * OUTD + tid];
        out[g * OUTD + tid] = a;
    }
}

// ---------------- launch ----------------
extern "C" void kernel_launch(void* const* d_in, const int* in_sizes, int n_in,
                              void* d_out, int out_size) {
    const float* x   = (const float*)d_in[0];
    const void*  ei  = d_in[1];
    const void*  bt  = d_in[2];
    const float* ew  = (const float*)d_in[3];
    const float* W1  = (const float*)d_in[4];
    const float* b1  = (const float*)d_in[5];
    const float* W2  = (const float*)d_in[6];
    const float* b2  = (const float*)d_in[7];
    const float* Wm1 = (const float*)d_in[8];
    const float* bm1 = (const float*)d_in[9];
    const float* Wm2 = (const float*)d_in[10];
    const float* bm2 = (const float*)d_in[11];
    float* out = (float*)d_out;

    k_detect<<<1, 32>>>((const unsigned*)ei);
    k_convert<<<(NE + 255) / 256, 256>>>(ei, bt);
    k_deg<<<(NE + 255) / 256, 256>>>(ew);
    k_dinv<<<(NN + 255) / 256, 256>>>();
    k_scan<<<1, 1024>>>();
    k_scatter<<<(NE + 255) / 256, 256>>>(ew);
    k_gemm_in<<<(NN + 31) / 32, 256>>>(x, W1);
    k_agg<<<(NN * 32 + 255) / 256, 256>>>(b1, 0);
    k_gemm_hid<<<(NN + 31) / 32, 256>>>(W2);
    k_agg<<<(NN * 32 + 255) / 256, 256>>>(b2, 1);
    k_pool<<<(NN * 32 + 255) / 256, 256>>>();
    k_mlp<<<NG, 128>>>(Wm1, bm1, Wm2, bm2, out);
}

// round 2
// speedup vs baseline: 1.4516x; 1.4516x over previous
#include <cuda_runtime.h>

#define NN   50000
#define NE   1600000
#define NG   512
#define IND  64
#define HID  128
#define OUTD 10
#define SCAN_B 1024
#define NBLK ((NN + SCAN_B - 1) / SCAN_B)   // 49

// ---------------- scratch (static __device__ — no allocation) ----------------
__device__ int   g_is64;
__device__ int   g_src[NE];
__device__ int   g_dst[NE];
__device__ float g_deg[NN];
__device__ float g_dinv[NN];
__device__ int   g_count[NN];
__device__ int   g_rowptr[NN + 1];
__device__ int   g_cursor[NN];
__device__ int2  g_edge[NE];          // (src, norm-as-int) packed
__device__ int   g_bsum[NBLK];
__device__ int   g_boff[NBLK];
__device__ int   g_gcount[NG];
__device__ int   g_gptr[NG + 1];
__device__ float g_ax[NN * IND];      // S @ x   (aggregated input features)
__device__ float g_a1[NN * HID];      // relu(g_ax @ W1 + b1)
__device__ float g_h2[NN * HID];      // g_a1 @ W2
__device__ float g_a2[NN * HID];      // relu(S @ h2 + b2)
__device__ float g_pool[NG * HID];

// ---------------- init + dtype detect ----------------
__global__ void k_init(const unsigned* __restrict__ ei_words) {
    int i = blockIdx.x * blockDim.x + threadIdx.x;
    if (i < NN) { g_deg[i] = 1.0f; g_count[i] = 0; }   // self-loop weight 1
    if (i < NG) g_gcount[i] = 0;
    if (i == 0) {
        int is64 = 1;
        #pragma unroll 1
        for (int k = 0; k < 128; k++)
            if (ei_words[2 * k + 1] != 0u) { is64 = 0; break; }
        g_is64 = is64;
    }
}

// ---------------- convert + degree/count histogram + batch histogram ----------------
__global__ void k_convert(const void* __restrict__ ei, const void* __restrict__ batch,
                          const float* __restrict__ ew) {
    int i = blockIdx.x * blockDim.x + threadIdx.x;
    int is64 = g_is64;
    if (i < NE) {
        int s, d;
        if (is64) {
            const long long* p = (const long long*)ei;
            s = (int)p[i]; d = (int)p[NE + i];
        } else {
            const int* p = (const int*)ei;
            s = p[i]; d = p[NE + i];
        }
        g_src[i] = s; g_dst[i] = d;
        atomicAdd(&g_deg[d], ew[i]);
        atomicAdd(&g_count[d], 1);
    }
    if (i < NN) {
        int b = is64 ? (int)((const long long*)batch)[i] : ((const int*)batch)[i];
        atomicAdd(&g_gcount[b], 1);
    }
}

__global__ void k_dinv() {
    int i = blockIdx.x * blockDim.x + threadIdx.x;
    if (i < NN) g_dinv[i] = rsqrtf(g_deg[i]);   // deg >= 1 (self-loop)
}

// ---------------- parallel exclusive scan: counts -> rowptr ----------------
__global__ void __launch_bounds__(SCAN_B) k_scanA() {
    __shared__ int s[SCAN_B];
    int tid = threadIdx.x;
    int idx = blockIdx.x * SCAN_B + tid;
    int v = (idx < NN) ? g_count[idx] : 0;
    s[tid] = v;
    __syncthreads();
    #pragma unroll
    for (int off = 1; off < SCAN_B; off <<= 1) {
        int t = (tid >= off) ? s[tid - off] : 0;
        __syncthreads();
        s[tid] += t;
        __syncthreads();
    }
    if (idx < NN) g_rowptr[idx] = s[tid] - v;   // block-local exclusive
    if (tid == SCAN_B - 1) g_bsum[blockIdx.x] = s[SCAN_B - 1];
}

__global__ void __launch_bounds__(512) k_scanB() {
    __shared__ int s[512];
    __shared__ int b[NBLK];
    int tid = threadIdx.x;
    // exclusive scan of graph histogram (512 bins)
    int gv = g_gcount[tid];
    s[tid] = gv;
    __syncthreads();
    #pragma unroll
    for (int off = 1; off < 512; off <<= 1) {
        int t = (tid >= off) ? s[tid - off] : 0;
        __syncthreads();
        s[tid] += t;
        __syncthreads();
    }
    g_gptr[tid] = s[tid] - gv;
    if (tid == 0) g_gptr[NG] = NN;
    // serial scan of 49 block sums (in shared — cheap)
    if (tid < NBLK) b[tid] = g_bsum[tid];
    __syncthreads();
    if (tid == 0) {
        int run = 0;
        #pragma unroll 1
        for (int i = 0; i < NBLK; i++) { int v = b[i]; b[i] = run; run += v; }
    }
    __syncthreads();
    if (tid < NBLK) g_boff[tid] = b[tid];
}

__global__ void __launch_bounds__(SCAN_B) k_scanC() {
    int tid = threadIdx.x;
    int idx = blockIdx.x * SCAN_B + tid;
    if (idx < NN) {
        int v = g_rowptr[idx] + g_boff[blockIdx.x];
        g_rowptr[idx] = v;
        g_cursor[idx] = v;
    }
    if (idx == 0) g_rowptr[NN] = NE;
}

// ---------------- scatter edges into CSR buckets with precomputed norm ----------------
__global__ void k_scatter(const float* __restrict__ ew) {
    int e = blockIdx.x * blockDim.x + threadIdx.x;
    if (e >= NE) return;
    int s = g_src[e];
    int d = g_dst[e];
    float nrm = g_dinv[s] * ew[e] * g_dinv[d];
    int pos = atomicAdd(&g_cursor[d], 1);
    g_edge[pos] = make_int2(s, __float_as_int(nrm));
}

// ---------------- layer-1 aggregation in INPUT space: g_ax = S @ x (64-dim) ----------------
// one warp per node; lanes hold a float2 slice of the 64-wide feature.
__global__ void __launch_bounds__(256) k_aggx(const float* __restrict__ x) {
    int node = (blockIdx.x * 256 + threadIdx.x) >> 5;
    int lane = threadIdx.x & 31;
    if (node >= NN) return;
    const float2* h = (const float2*)x;
    float d = g_dinv[node];
    float sl = d * d;
    float2 acc = h[node * 32 + lane];
    acc.x *= sl; acc.y *= sl;
    int e   = g_rowptr[node];
    int end = g_rowptr[node + 1];
    #pragma unroll 4
    for (; e < end; e++) {
        int2 ed = __ldg(&g_edge[e]);            // warp-uniform broadcast
        float nm = __int_as_float(ed.y);
        float2 hs = h[ed.x * 32 + lane];        // L2-resident gather (256B/warp)
        acc.x += hs.x * nm; acc.y += hs.y * nm;
    }
    ((float2*)g_ax)[node * 32 + lane] = acc;
}

// ---------------- GEMM: a1 = relu(g_ax @ W1 + b1)  (50000 x 64 @ 64 x 128) ----------------
__global__ void __launch_bounds__(256) k_gemm_in(const float* __restrict__ W,
                                                 const float* __restrict__ bias) {
    __shared__ float Ws[IND * HID];   // 32 KB
    __shared__ float xs[32 * IND];    //  8 KB
    int tid = threadIdx.x;
    int row0 = blockIdx.x * 32;
    for (int i = tid; i < IND * HID / 4; i += 256)
        ((float4*)Ws)[i] = ((const float4*)W)[i];
    for (int i = tid; i < 32 * IND / 4; i += 256) {
        int row = row0 + i / (IND / 4);
        float4 v = make_float4(0.f, 0.f, 0.f, 0.f);
        if (row < NN) v = ((const float4*)g_ax)[row * (IND / 4) + (i % (IND / 4))];
        ((float4*)xs)[i] = v;
    }
    __syncthreads();
    int warp = tid >> 5, lane = tid & 31;
    int rbase = warp * 4;
    float4 acc[4];
    #pragma unroll
    for (int r = 0; r < 4; r++) acc[r] = make_float4(0.f, 0.f, 0.f, 0.f);
    #pragma unroll 4
    for (int k = 0; k < IND; k++) {
        float4 w = ((float4*)Ws)[k * 32 + lane];
        #pragma unroll
        for (int r = 0; r < 4; r++) {
            float xv = xs[(rbase + r) * IND + k];
            acc[r].x += xv * w.x; acc[r].y += xv * w.y;
            acc[r].z += xv * w.z; acc[r].w += xv * w.w;
        }
    }
    float4 bv = ((const float4*)bias)[lane];
    #pragma unroll
    for (int r = 0; r < 4; r++) {
        int row = row0 + rbase + r;
        if (row < NN) {
            float4 o;
            o.x = fmaxf(acc[r].x + bv.x, 0.f);
            o.y = fmaxf(acc[r].y + bv.y, 0.f);
            o.z = fmaxf(acc[r].z + bv.z, 0.f);
            o.w = fmaxf(acc[r].w + bv.w, 0.f);
            ((float4*)g_a1)[row * 32 + lane] = o;
        }
    }
}

// ---------------- GEMM: h2 = a1 @ W2   (50000 x 128 @ 128 x 128) ----------------
__global__ void __launch_bounds__(256) k_gemm_hid(const float* __restrict__ W) {
    __shared__ float Ws[64 * HID];    // 32 KB (one K-chunk of W2)
    __shared__ float xs[32 * HID];    // 16 KB
    int tid = threadIdx.x;
    int row0 = blockIdx.x * 32;
    for (int i = tid; i < 32 * HID / 4; i += 256) {
        int row = row0 + i / (HID / 4);
        float4 v = make_float4(0.f, 0.f, 0.f, 0.f);
        if (row < NN) v = ((const float4*)g_a1)[row * (HID / 4) + (i % (HID / 4))];
        ((float4*)xs)[i] = v;
    }
    int warp = tid >> 5, lane = tid & 31;
    int rbase = warp * 4;
    float4 acc[4];
    #pragma unroll
    for (int r = 0; r < 4; r++) acc[r] = make_float4(0.f, 0.f, 0.f, 0.f);
    for (int c = 0; c < 2; c++) {
        __syncthreads();
        for (int i = tid; i < 64 * HID / 4; i += 256)
            ((float4*)Ws)[i] = ((const float4*)(W + c * 64 * HID))[i];
        __syncthreads();
        #pragma unroll 4
        for (int k = 0; k < 64; k++) {
            int kk = c * 64 + k;
            float4 w = ((float4*)Ws)[k * 32 + lane];
            #pragma unroll
            for (int r = 0; r < 4; r++) {
                float xv = xs[(rbase + r) * HID + kk];
                acc[r].x += xv * w.x; acc[r].y += xv * w.y;
                acc[r].z += xv * w.z; acc[r].w += xv * w.w;
            }
        }
    }
    #pragma unroll
    for (int r = 0; r < 4; r++) {
        int row = row0 + rbase + r;
        if (row < NN) ((float4*)g_h2)[row * 32 + lane] = acc[r];
    }
}

// ---------------- layer-2 aggregation: a2 = relu(S @ h2 + b2) (128-dim) ----------------
__global__ void __launch_bounds__(256) k_agg128(const float* __restrict__ bias) {
    int node = (blockIdx.x * 256 + threadIdx.x) >> 5;
    int lane = threadIdx.x & 31;
    if (node >= NN) return;
    const float4* h = (const float4*)g_h2;
    float d = g_dinv[node];
    float sl = d * d;
    float4 acc = h[node * 32 + lane];
    acc.x *= sl; acc.y *= sl; acc.z *= sl; acc.w *= sl;
    int e   = g_rowptr[node];
    int end = g_rowptr[node + 1];
    #pragma unroll 4
    for (; e < end; e++) {
        int2 ed = __ldg(&g_edge[e]);
        float nm = __int_as_float(ed.y);
        float4 hs = h[ed.x * 32 + lane];        // 512B/warp gather, L2 resident
        acc.x += hs.x * nm; acc.y += hs.y * nm;
        acc.z += hs.z * nm; acc.w += hs.w * nm;
    }
    float4 b = ((const float4*)bias)[lane];
    acc.x = fmaxf(acc.x + b.x, 0.f);
    acc.y = fmaxf(acc.y + b.y, 0.f);
    acc.z = fmaxf(acc.z + b.z, 0.f);
    acc.w = fmaxf(acc.w + b.w, 0.f);
    ((float4*)g_a2)[node * 32 + lane] = acc;
}

// ---------------- atomic-free pool: batch is SORTED -> contiguous node ranges ----------------
__global__ void __launch_bounds__(128) k_pool() {
    int g = blockIdx.x;
    int tid = threadIdx.x;
    int n0 = g_gptr[g], n1 = g_gptr[g + 1];
    float acc = 0.f;
    for (int n = n0; n < n1; n++)
        acc += g_a2[n * HID + tid];             // coalesced 512B rows
    g_pool[g * HID + tid] = acc;
}

// ---------------- MLP head ----------------
__global__ void __launch_bounds__(128) k_mlp(const float* __restrict__ Wm1,
                                             const float* __restrict__ bm1,
                                             const float* __restrict__ Wm2,
                                             const float* __restrict__ bm2,
                                             float* __restrict__ out) {
    int g = blockIdx.x;
    int tid = threadIdx.x;
    __shared__ float ps[HID];
    __shared__ float zs[HID];
    ps[tid] = g_pool[g * HID + tid];
    __syncthreads();
    float acc = bm1[tid];
    #pragma unroll 8
    for (int k = 0; k < HID; k++) acc += ps[k] * Wm1[k * HID + tid];
    zs[tid] = fmaxf(acc, 0.f);
    __syncthreads();
    if (tid < OUTD) {
        float a = bm2[tid];
        #pragma unroll 8
        for (int k = 0; k < HID; k++) a += zs[k] * Wm2[k * OUTD + tid];
        out[g * OUTD + tid] = a;
    }
}

// ---------------- launch ----------------
extern "C" void kernel_launch(void* const* d_in, const int* in_sizes, int n_in,
                              void* d_out, int out_size) {
    const float* x   = (const float*)d_in[0];
    const void*  ei  = d_in[1];
    const void*  bt  = d_in[2];
    const float* ew  = (const float*)d_in[3];
    const float* W1  = (const float*)d_in[4];
    const float* b1  = (const float*)d_in[5];
    const float* W2  = (const float*)d_in[6];
    const float* b2  = (const float*)d_in[7];
    const float* Wm1 = (const float*)d_in[8];
    const float* bm1 = (const float*)d_in[9];
    const float* Wm2 = (const float*)d_in[10];
    const float* bm2 = (const float*)d_in[11];
    float* out = (float*)d_out;

    k_init<<<(NN + 255) / 256, 256>>>((const unsigned*)ei);
    k_convert<<<(NE + 255) / 256, 256>>>(ei, bt, ew);
    k_dinv<<<(NN + 255) / 256, 256>>>();
    k_scanA<<<NBLK, SCAN_B>>>();
    k_scanB<<<1, 512>>>();
    k_scanC<<<NBLK, SCAN_B>>>();
    k_scatter<<<(NE + 255) / 256, 256>>>(ew);
    k_aggx<<<(NN * 32 + 255) / 256, 256>>>(x);
    k_gemm_in<<<(NN + 31) / 32, 256>>>(W1, b1);
    k_gemm_hid<<<(NN + 31) / 32, 256>>>(W2);
    k_agg128<<<(NN * 32 + 255) / 256, 256>>>(b2);
    k_pool<<<NG, 128>>>();
    k_mlp<<<NG, 128>>>(Wm1, bm1, Wm2, bm2, out);
}

// round 3
// speedup vs baseline: 1.5036x; 1.0358x over previous
#include <cuda_runtime.h>
#include <cuda_fp16.h>

#define NN   50000
#define NE   1600000
#define NG   512
#define IND  64
#define HID  128
#define OUTD 10
#define SCAN_B 1024
#define NBLK ((NN + SCAN_B - 1) / SCAN_B)   // 49

// ---------------- scratch (static __device__ — no allocation) ----------------
__device__ int    g_is64;
__device__ float  g_dinv[NN];
__device__ int    g_count[NN];
__device__ int    g_rowptr[NN + 1];
__device__ int    g_cursor[NN];
__device__ int2   g_edge[NE];         // (src, edge_weight bits)
__device__ int    g_bsum[NBLK];
__device__ int    g_boff[NBLK];
__device__ int    g_gcount[NG];
__device__ int    g_gptr[NG + 1];
__device__ __half g_xh[NN * IND];     // fp16 copy of x for gather
__device__ float  g_ax[NN * IND];     // S @ x
__device__ float  g_a1[NN * HID];     // relu(g_ax @ W1 + b1)
__device__ __half g_h2h[NN * HID];    // fp16(a1 @ W2) for gather
__device__ float  g_a2[NN * HID];     // relu(S @ h2 + b2)
__device__ float  g_pool[NG * HID];

// ---------------- init + dtype detect ----------------
__global__ void k_init(const unsigned* __restrict__ ei_words) {
    int i = blockIdx.x * blockDim.x + threadIdx.x;
    if (i < NN) g_count[i] = 0;
    if (i < NG) g_gcount[i] = 0;
    if (i == 0) {
        int is64 = 1;
        #pragma unroll 1
        for (int k = 0; k < 128; k++)
            if (ei_words[2 * k + 1] != 0u) { is64 = 0; break; }
        g_is64 = is64;
    }
}

// ---------------- fp16 copy of x ----------------
__global__ void k_xhalf(const float* __restrict__ x) {
    int i = blockIdx.x * blockDim.x + threadIdx.x;   // over NN*IND/2 half2
    if (i < NN * IND / 2) {
        float2 v = ((const float2*)x)[i];
        ((__half2*)g_xh)[i] = __floats2half2_rn(v.x, v.y);
    }
}

// ---------------- in-degree histogram + batch histogram ----------------
__global__ void k_hist(const void* __restrict__ ei, const void* __restrict__ batch) {
    int i = blockIdx.x * blockDim.x + threadIdx.x;
    int is64 = g_is64;
    if (i < NE) {
        int d = is64 ? (int)((const long long*)ei)[NE + i] : ((const int*)ei)[NE + i];
        atomicAdd(&g_count[d], 1);
    }
    if (i < NN) {
        int b = is64 ? (int)((const long long*)batch)[i] : ((const int*)batch)[i];
        atomicAdd(&g_gcount[b], 1);
    }
}

// ---------------- parallel exclusive scan: counts -> rowptr ----------------
__global__ void __launch_bounds__(SCAN_B) k_scanA() {
    __shared__ int s[SCAN_B];
    int tid = threadIdx.x;
    int idx = blockIdx.x * SCAN_B + tid;
    int v = (idx < NN) ? g_count[idx] : 0;
    s[tid] = v;
    __syncthreads();
    #pragma unroll
    for (int off = 1; off < SCAN_B; off <<= 1) {
        int t = (tid >= off) ? s[tid - off] : 0;
        __syncthreads();
        s[tid] += t;
        __syncthreads();
    }
    if (idx < NN) g_rowptr[idx] = s[tid] - v;   // block-local exclusive
    if (tid == SCAN_B - 1) g_bsum[blockIdx.x] = s[SCAN_B - 1];
}

__global__ void __launch_bounds__(512) k_scanB() {
    __shared__ int s[512];
    __shared__ int b[NBLK];
    int tid = threadIdx.x;
    int gv = g_gcount[tid];
    s[tid] = gv;
    __syncthreads();
    #pragma unroll
    for (int off = 1; off < 512; off <<= 1) {
        int t = (tid >= off) ? s[tid - off] : 0;
        __syncthreads();
        s[tid] += t;
        __syncthreads();
    }
    g_gptr[tid] = s[tid] - gv;
    if (tid == 0) g_gptr[NG] = NN;
    if (tid < NBLK) b[tid] = g_bsum[tid];
    __syncthreads();
    if (tid == 0) {
        int run = 0;
        #pragma unroll 1
        for (int i = 0; i < NBLK; i++) { int v = b[i]; b[i] = run; run += v; }
    }
    __syncthreads();
    if (tid < NBLK) g_boff[tid] = b[tid];
}

__global__ void __launch_bounds__(SCAN_B) k_scanC() {
    int tid = threadIdx.x;
    int idx = blockIdx.x * SCAN_B + tid;
    if (idx < NN) {
        int v = g_rowptr[idx] + g_boff[blockIdx.x];
        g_rowptr[idx] = v;
        g_cursor[idx] = v;
    }
    if (idx == 0) g_rowptr[NN] = NE;
}

// ---------------- scatter edges into CSR buckets (src, ew) ----------------
__global__ void k_scatter(const void* __restrict__ ei, const float* __restrict__ ew) {
    int e = blockIdx.x * blockDim.x + threadIdx.x;
    if (e >= NE) return;
    int s, d;
    if (g_is64) {
        const long long* p = (const long long*)ei;
        s = (int)p[e]; d = (int)p[NE + e];
    } else {
        const int* p = (const int*)ei;
        s = p[e]; d = p[NE + e];
    }
    int pos = atomicAdd(&g_cursor[d], 1);
    g_edge[pos] = make_int2(s, __float_as_int(ew[e]));
}

// ---------------- degree from CSR (no atomics) + dinv ----------------
__global__ void __launch_bounds__(256) k_deg() {
    int node = (blockIdx.x * 256 + threadIdx.x) >> 5;
    int lane = threadIdx.x & 31;
    if (node >= NN) return;
    int e0 = g_rowptr[node], e1 = g_rowptr[node + 1];
    float sum = 0.f;
    for (int e = e0 + lane; e < e1; e += 32)
        sum += __int_as_float(g_edge[e].y);
    #pragma unroll
    for (int off = 16; off > 0; off >>= 1)
        sum += __shfl_down_sync(0xffffffffu, sum, off);
    if (lane == 0)
        g_dinv[node] = rsqrtf(1.0f + sum);      // self-loop weight 1
}

// ---------------- layer-1 aggregation: g_ax = S @ x (fp16 gather, 64-dim) ----------------
__global__ void __launch_bounds__(256) k_aggx(const float* __restrict__ x) {
    int node = (blockIdx.x * 256 + threadIdx.x) >> 5;
    int lane = threadIdx.x & 31;
    if (node >= NN) return;
    float dn = g_dinv[node];
    float sl = dn * dn;
    float2 self = ((const float2*)x)[node * 32 + lane];   // exact fp32 self term
    float2 acc = make_float2(self.x * sl, self.y * sl);
    int e   = g_rowptr[node];
    int end = g_rowptr[node + 1];
    #pragma unroll 4
    for (; e < end; e++) {
        int2 ed = __ldg(&g_edge[e]);                       // broadcast
        float nm = __ldg(&g_dinv[ed.x]) * __int_as_float(ed.y) * dn;
        float2 hs = __half22float2(((const __half2*)g_xh)[ed.x * 32 + lane]);  // 128B/warp
        acc.x += hs.x * nm; acc.y += hs.y * nm;
    }
    ((float2*)g_ax)[node * 32 + lane] = acc;
}

// ---------------- GEMM: a1 = relu(g_ax @ W1 + b1)  (50000 x 64 @ 64 x 128) ----------------
__global__ void __launch_bounds__(256) k_gemm_in(const float* __restrict__ W,
                                                 const float* __restrict__ bias) {
    __shared__ float Ws[IND * HID];   // 32 KB
    __shared__ float xs[32 * IND];    //  8 KB
    int tid = threadIdx.x;
    int row0 = blockIdx.x * 32;
    for (int i = tid; i < IND * HID / 4; i += 256)
        ((float4*)Ws)[i] = ((const float4*)W)[i];
    for (int i = tid; i < 32 * IND / 4; i += 256) {
        int row = row0 + i / (IND / 4);
        float4 v = make_float4(0.f, 0.f, 0.f, 0.f);
        if (row < NN) v = ((const float4*)g_ax)[row * (IND / 4) + (i % (IND / 4))];
        ((float4*)xs)[i] = v;
    }
    __syncthreads();
    int warp = tid >> 5, lane = tid & 31;
    int rbase = warp * 4;
    float4 acc[4];
    #pragma unroll
    for (int r = 0; r < 4; r++) acc[r] = make_float4(0.f, 0.f, 0.f, 0.f);
    #pragma unroll 4
    for (int k = 0; k < IND; k++) {
        float4 w = ((float4*)Ws)[k * 32 + lane];
        #pragma unroll
        for (int r = 0; r < 4; r++) {
            float xv = xs[(rbase + r) * IND + k];
            acc[r].x += xv * w.x; acc[r].y += xv * w.y;
            acc[r].z += xv * w.z; acc[r].w += xv * w.w;
        }
    }
    float4 bv = ((const float4*)bias)[lane];
    #pragma unroll
    for (int r = 0; r < 4; r++) {
        int row = row0 + rbase + r;
        if (row < NN) {
            float4 o;
            o.x = fmaxf(acc[r].x + bv.x, 0.f);
            o.y = fmaxf(acc[r].y + bv.y, 0.f);
            o.z = fmaxf(acc[r].z + bv.z, 0.f);
            o.w = fmaxf(acc[r].w + bv.w, 0.f);
            ((float4*)g_a1)[row * 32 + lane] = o;
        }
    }
}

// ---------------- GEMM: h2h = fp16(a1 @ W2)  (50000 x 128 @ 128 x 128) ----------------
__global__ void __launch_bounds__(256) k_gemm_hid(const float* __restrict__ W) {
    __shared__ float Ws[64 * HID];    // 32 KB (one K-chunk)
    __shared__ float xs[32 * HID];    // 16 KB
    int tid = threadIdx.x;
    int row0 = blockIdx.x * 32;
    for (int i = tid; i < 32 * HID / 4; i += 256) {
        int row = row0 + i / (HID / 4);
        float4 v = make_float4(0.f, 0.f, 0.f, 0.f);
        if (row < NN) v = ((const float4*)g_a1)[row * (HID / 4) + (i % (HID / 4))];
        ((float4*)xs)[i] = v;
    }
    int warp = tid >> 5, lane = tid & 31;
    int rbase = warp * 4;
    float4 acc[4];
    #pragma unroll
    for (int r = 0; r < 4; r++) acc[r] = make_float4(0.f, 0.f, 0.f, 0.f);
    for (int c = 0; c < 2; c++) {
        __syncthreads();
        for (int i = tid; i < 64 * HID / 4; i += 256)
            ((float4*)Ws)[i] = ((const float4*)(W + c * 64 * HID))[i];
        __syncthreads();
        #pragma unroll 4
        for (int k = 0; k < 64; k++) {
            int kk = c * 64 + k;
            float4 w = ((float4*)Ws)[k * 32 + lane];
            #pragma unroll
            for (int r = 0; r < 4; r++) {
                float xv = xs[(rbase + r) * HID + kk];
                acc[r].x += xv * w.x; acc[r].y += xv * w.y;
                acc[r].z += xv * w.z; acc[r].w += xv * w.w;
            }
        }
    }
    #pragma unroll
    for (int r = 0; r < 4; r++) {
        int row = row0 + rbase + r;
        if (row < NN) {
            uint2 pk;
            __half2 h0 = __floats2half2_rn(acc[r].x, acc[r].y);
            __half2 h1 = __floats2half2_rn(acc[r].z, acc[r].w);
            pk.x = *(unsigned*)&h0;
            pk.y = *(unsigned*)&h1;
            ((uint2*)g_h2h)[row * 32 + lane] = pk;
        }
    }
}

// ---------------- layer-2 aggregation: a2 = relu(S @ h2 + b2) (fp16 gather, 128-dim) ----------------
__global__ void __launch_bounds__(256) k_agg128(const float* __restrict__ bias) {
    int node = (blockIdx.x * 256 + threadIdx.x) >> 5;
    int lane = threadIdx.x & 31;
    if (node >= NN) return;
    float dn = g_dinv[node];
    float sl = dn * dn;
    uint2 sv = ((const uint2*)g_h2h)[node * 32 + lane];
    float2 s0 = __half22float2(*(__half2*)&sv.x);
    float2 s1 = __half22float2(*(__half2*)&sv.y);
    float4 acc = make_float4(s0.x * sl, s0.y * sl, s1.x * sl, s1.y * sl);
    int e   = g_rowptr[node];
    int end = g_rowptr[node + 1];
    #pragma unroll 4
    for (; e < end; e++) {
        int2 ed = __ldg(&g_edge[e]);
        float nm = __ldg(&g_dinv[ed.x]) * __int_as_float(ed.y) * dn;
        uint2 hv = ((const uint2*)g_h2h)[ed.x * 32 + lane];   // 256B/warp gather
        float2 f0 = __half22float2(*(__half2*)&hv.x);
        float2 f1 = __half22float2(*(__half2*)&hv.y);
        acc.x += f0.x * nm; acc.y += f0.y * nm;
        acc.z += f1.x * nm; acc.w += f1.y * nm;
    }
    float4 b = ((const float4*)bias)[lane];
    acc.x = fmaxf(acc.x + b.x, 0.f);
    acc.y = fmaxf(acc.y + b.y, 0.f);
    acc.z = fmaxf(acc.z + b.z, 0.f);
    acc.w = fmaxf(acc.w + b.w, 0.f);
    ((float4*)g_a2)[node * 32 + lane] = acc;
}

// ---------------- atomic-free pool: batch sorted -> contiguous ranges ----------------
__global__ void __launch_bounds__(128) k_pool() {
    int g = blockIdx.x;
    int tid = threadIdx.x;
    int n0 = g_gptr[g], n1 = g_gptr[g + 1];
    float acc = 0.f;
    for (int n = n0; n < n1; n++)
        acc += g_a2[n * HID + tid];
    g_pool[g * HID + tid] = acc;
}

// ---------------- MLP head ----------------
__global__ void __launch_bounds__(128) k_mlp(const float* __restrict__ Wm1,
                                             const float* __restrict__ bm1,
                                             const float* __restrict__ Wm2,
                                             const float* __restrict__ bm2,
                                             float* __restrict__ out) {
    int g = blockIdx.x;
    int tid = threadIdx.x;
    __shared__ float ps[HID];
    __shared__ float zs[HID];
    ps[tid] = g_pool[g * HID + tid];
    __syncthreads();
    float acc = bm1[tid];
    #pragma unroll 8
    for (int k = 0; k < HID; k++) acc += ps[k] * Wm1[k * HID + tid];
    zs[tid] = fmaxf(acc, 0.f);
    __syncthreads();
    if (tid < OUTD) {
        float a = bm2[tid];
        #pragma unroll 8
        for (int k = 0; k < HID; k++) a += zs[k] * Wm2[k * OUTD + tid];
        out[g * OUTD + tid] = a;
    }
}

// ---------------- launch ----------------
extern "C" void kernel_launch(void* const* d_in, const int* in_sizes, int n_in,
                              void* d_out, int out_size) {
    const float* x   = (const float*)d_in[0];
    const void*  ei  = d_in[1];
    const void*  bt  = d_in[2];
    const float* ew  = (const float*)d_in[3];
    const float* W1  = (const float*)d_in[4];
    const float* b1  = (const float*)d_in[5];
    const float* W2  = (const float*)d_in[6];
    const float* b2  = (const float*)d_in[7];
    const float* Wm1 = (const float*)d_in[8];
    const float* bm1 = (const float*)d_in[9];
    const float* Wm2 = (const float*)d_in[10];
    const float* bm2 = (const float*)d_in[11];
    float* out = (float*)d_out;

    k_init<<<(NN + 255) / 256, 256>>>((const unsigned*)ei);
    k_xhalf<<<(NN * IND / 2 + 255) / 256, 256>>>(x);
    k_hist<<<(NE + 255) / 256, 256>>>(ei, bt);
    k_scanA<<<NBLK, SCAN_B>>>();
    k_scanB<<<1, 512>>>();
    k_scanC<<<NBLK, SCAN_B>>>();
    k_scatter<<<(NE + 255) / 256, 256>>>(ei, ew);
    k_deg<<<(NN * 32 + 255) / 256, 256>>>();
    k_aggx<<<(NN * 32 + 255) / 256, 256>>>(x);
    k_gemm_in<<<(NN + 31) / 32, 256>>>(W1, b1);
    k_gemm_hid<<<(NN + 31) / 32, 256>>>(W2);
    k_agg128<<<(NN * 32 + 255) / 256, 256>>>(b2);
    k_pool<<<NG, 128>>>();
    k_mlp<<<NG, 128>>>(Wm1, bm1, Wm2, bm2, out);
}

// round 5
// speedup vs baseline: 1.9960x; 1.3275x over previous
#include <cuda_runtime.h>
#include <cuda_fp16.h>
#include <cstdint>

#define NN   50000
#define NE   1600000
#define NG   512
#define IND  64
#define HID  128
#define OUTD 10
#define SCAN_B 1024
#define NBLK ((NN + SCAN_B - 1) / SCAN_B)   // 49

// ---------------- scratch (static __device__, zero-initialized; every kernel
// restores what it consumes so the graph can be replayed indefinitely) --------
__device__ int    g_is64;
__device__ float  g_deg[NN];          // starts 0; dinv resets to 0 after use
__device__ float  g_dinv[NN];
__device__ int    g_count[NN];        // starts 0; scanA resets
__device__ int    g_rowptr[NN + 1];
__device__ int    g_cursor[NN];
__device__ int2   g_edge[NE];         // (src, norm bits)
__device__ int    g_bsum[NBLK];
__device__ int    g_boff[NBLK];
__device__ int    g_gcount[NG];       // starts 0; scanB resets
__device__ int    g_gptr[NG + 1];
__device__ __half g_xh[NN * IND];     // fp16 x for gather
__device__ __half g_w1h[IND * HID];
__device__ __half g_w2h[HID * HID];
__device__ __half g_axh[NN * IND];    // fp16 S @ x
__device__ __half g_a1h[NN * HID];    // fp16 relu(axh @ W1 + b1)
__device__ __half g_h2h[NN * HID];    // fp16 (a1 @ W2)
__device__ float  g_a2[NN * HID];     // fp32 relu(S @ h2 + b2)

// ---------------- pre: x->fp16, W1/W2->fp16, is64 detect ----------------
__global__ void k_pre(const float* __restrict__ x, const float* __restrict__ W1,
                      const float* __restrict__ W2, const unsigned* __restrict__ ei_words) {
    int i = blockIdx.x * blockDim.x + threadIdx.x;
    if (i < NN * IND / 2) {
        float2 v = ((const float2*)x)[i];
        ((__half2*)g_xh)[i] = __floats2half2_rn(v.x, v.y);
    }
    if (i < IND * HID / 2) {
        float2 v = ((const float2*)W1)[i];
        ((__half2*)g_w1h)[i] = __floats2half2_rn(v.x, v.y);
    }
    if (i < HID * HID / 2) {
        float2 v = ((const float2*)W2)[i];
        ((__half2*)g_w2h)[i] = __floats2half2_rn(v.x, v.y);
    }
    if (i == 0) {
        int is64 = 1;
        #pragma unroll 1
        for (int k = 0; k < 128; k++)
            if (ei_words[2 * k + 1] != 0u) { is64 = 0; break; }
        g_is64 = is64;
    }
}

// ---------------- histograms: weighted degree, in-degree count, batch ----------------
__global__ void k_hist(const void* __restrict__ ei, const void* __restrict__ batch,
                       const float* __restrict__ ew) {
    int i = blockIdx.x * blockDim.x + threadIdx.x;
    int is64 = g_is64;
    if (i < NE) {
        int d = is64 ? (int)((const long long*)ei)[NE + i] : ((const int*)ei)[NE + i];
        atomicAdd(&g_deg[d], ew[i]);
        atomicAdd(&g_count[d], 1);
    }
    if (i < NN) {
        int b = is64 ? (int)((const long long*)batch)[i] : ((const int*)batch)[i];
        atomicAdd(&g_gcount[b], 1);
    }
}

__global__ void k_dinv() {
    int i = blockIdx.x * blockDim.x + threadIdx.x;
    if (i < NN) {
        g_dinv[i] = rsqrtf(1.0f + g_deg[i]);   // self-loop weight 1
        g_deg[i] = 0.0f;                       // restore for next replay
    }
}

// ---------------- scans ----------------
__global__ void __launch_bounds__(SCAN_B) k_scanA() {
    __shared__ int ws[32];
    int tid = threadIdx.x, lane = tid & 31, warp = tid >> 5;
    int idx = blockIdx.x * SCAN_B + tid;
    int v = (idx < NN) ? g_count[idx] : 0;
    if (idx < NN) g_count[idx] = 0;            // restore
    int xi = v;
    #pragma unroll
    for (int off = 1; off < 32; off <<= 1) {
        int t = __shfl_up_sync(0xffffffffu, xi, off);
        if (lane >= off) xi += t;
    }
    if (lane == 31) ws[warp] = xi;
    __syncthreads();
    if (warp == 0) {
        int y = ws[lane];
        #pragma unroll
        for (int off = 1; off < 32; off <<= 1) {
            int t = __shfl_up_sync(0xffffffffu, y, off);
            if (lane >= off) y += t;
        }
        ws[lane] = y;
    }
    __syncthreads();
    int incl = xi + (warp ? ws[warp - 1] : 0);
    if (idx < NN) g_rowptr[idx] = incl - v;
    if (tid == SCAN_B - 1) g_bsum[blockIdx.x] = incl;
}

__global__ void __launch_bounds__(512) k_scanB() {
    __shared__ int ws[16];
    __shared__ int b[NBLK];
    int tid = threadIdx.x, lane = tid & 31, warp = tid >> 5;
    int gv = g_gcount[tid];
    g_gcount[tid] = 0;                          // restore
    int xi = gv;
    #pragma unroll
    for (int off = 1; off < 32; off <<= 1) {
        int t = __shfl_up_sync(0xffffffffu, xi, off);
        if (lane >= off) xi += t;
    }
    if (lane == 31) ws[warp] = xi;
    __syncthreads();
    if (warp == 0 && lane < 16) {
        int y = ws[lane];
        #pragma unroll
        for (int off = 1; off < 16; off <<= 1) {
            int t = __shfl_up_sync(0xffffu, y, off);
            if (lane >= off) y += t;
        }
        ws[lane] = y;
    }
    __syncthreads();
    g_gptr[tid] = xi + (warp ? ws[warp - 1] : 0) - gv;
    if (tid == 0) g_gptr[NG] = NN;
    if (tid < NBLK) b[tid] = g_bsum[tid];
    __syncthreads();
    if (tid == 0) {
        int run = 0;
        #pragma unroll 1
        for (int i = 0; i < NBLK; i++) { int v = b[i]; b[i] = run; run += v; }
    }
    __syncthreads();
    if (tid < NBLK) g_boff[tid] = b[tid];
}

__global__ void __launch_bounds__(SCAN_B) k_scanC() {
    int idx = blockIdx.x * SCAN_B + threadIdx.x;
    if (idx < NN) {
        int v = g_rowptr[idx] + g_boff[blockIdx.x];
        g_rowptr[idx] = v;
        g_cursor[idx] = v;
    }
    if (idx == 0) g_rowptr[NN] = NE;
}

// ---------------- scatter edges with precomputed symmetric norm ----------------
__global__ void k_scatter(const void* __restrict__ ei, const float* __restrict__ ew) {
    int e = blockIdx.x * blockDim.x + threadIdx.x;
    if (e >= NE) return;
    int s, d;
    if (g_is64) {
        const long long* p = (const long long*)ei;
        s = (int)p[e]; d = (int)p[NE + e];
    } else {
        const int* p = (const int*)ei;
        s = p[e]; d = p[NE + e];
    }
    float nrm = g_dinv[s] * ew[e] * g_dinv[d];
    int pos = atomicAdd(&g_cursor[d], 1);
    g_edge[pos] = make_int2(s, __float_as_int(nrm));
}

// ---------------- layer-1 aggregation: axh = fp16(S @ x), 64-dim ----------------
__global__ void __launch_bounds__(256) k_aggx(const float* __restrict__ x) {
    int node = (blockIdx.x * 256 + threadIdx.x) >> 5;
    int lane = threadIdx.x & 31;
    if (node >= NN) return;
    float dn = g_dinv[node];
    float sl = dn * dn;
    float2 self = ((const float2*)x)[node * 32 + lane];
    float2 acc = make_float2(self.x * sl, self.y * sl);
    int e   = g_rowptr[node];
    int end = g_rowptr[node + 1];
    #pragma unroll 4
    for (; e < end; e++) {
        int2 ed = __ldg(&g_edge[e]);
        float nm = __int_as_float(ed.y);
        float2 hs = __half22float2(((const __half2*)g_xh)[ed.x * 32 + lane]);
        acc.x += hs.x * nm; acc.y += hs.y * nm;
    }
    ((__half2*)g_axh)[node * 32 + lane] = __floats2half2_rn(acc.x, acc.y);
}

// ---------------- tensor-core GEMM over device globals ----------------
// LAYER1: g_a1h = relu(g_axh[NN,64] @ g_w1h + b1) ; else: g_h2h = g_a1h[NN,128] @ g_w2h
// block = 256 thr (8 warps: 4 in M x 2 in N), tile 128x128, K staged in 64-chunks.
template<bool LAYER1>
__global__ void __launch_bounds__(256) k_gemm16(const float* __restrict__ bias) {
    constexpr int K   = LAYER1 ? IND : HID;
    constexpr int KC  = 64;
    constexpr int LDA = KC + 8;     // halves
    constexpr int LDB = 128 + 8;
    const __half* A = LAYER1 ? g_axh : g_a1h;   // device-side symbol refs (valid)
    const __half* W = LAYER1 ? g_w1h : g_w2h;
    __half* out     = LAYER1 ? g_a1h : g_h2h;
    __shared__ __half As[128 * LDA];
    __shared__ __half Bs[KC * LDB];
    int tid = threadIdx.x;
    int row0 = blockIdx.x * 128;
    int warp = tid >> 5, lane = tid & 31;
    int wm = (warp & 3) * 32;       // warp M offset: 2 x m16
    int wn = (warp >> 2) * 64;      // warp N offset: 8 x n8
    float acc[2][8][4];
    #pragma unroll
    for (int mi = 0; mi < 2; mi++)
        #pragma unroll
        for (int nj = 0; nj < 8; nj++)
            #pragma unroll
            for (int q = 0; q < 4; q++) acc[mi][nj][q] = 0.f;

    for (int kc = 0; kc < K; kc += KC) {
        // stage A chunk: 128 rows x 64 halves
        for (int i = tid; i < 128 * KC / 8; i += 256) {
            int r = i >> 3, c = (i & 7) * 8;
            uint4 v = make_uint4(0u, 0u, 0u, 0u);
            if (row0 + r < NN)
                v = ((const uint4*)A)[(row0 + r) * (K / 8) + (kc + c) / 8];
            *(uint4*)&As[r * LDA + c] = v;
        }
        // stage B chunk: 64 rows x 128 halves
        for (int i = tid; i < KC * 128 / 8; i += 256) {
            int r = i >> 4, c = (i & 15) * 8;
            *(uint4*)&Bs[r * LDB + c] = ((const uint4*)W)[((kc + r) * 128 + c) / 8];
        }
        __syncthreads();
        #pragma unroll
        for (int k = 0; k < KC; k += 16) {
            uint32_t a[2][4], b[4][4];
            #pragma unroll
            for (int mi = 0; mi < 2; mi++) {
                uint32_t addr = (uint32_t)__cvta_generic_to_shared(
                    &As[(wm + mi * 16 + (lane & 15)) * LDA + k + 8 * (lane >> 4)]);
                asm volatile("ldmatrix.sync.aligned.m8n8.x4.shared.b16 {%0,%1,%2,%3}, [%4];"
                             : "=r"(a[mi][0]), "=r"(a[mi][1]), "=r"(a[mi][2]), "=r"(a[mi][3])
                             : "r"(addr));
            }
            #pragma unroll
            for (int ni = 0; ni < 4; ni++) {
                uint32_t addr = (uint32_t)__cvta_generic_to_shared(
                    &Bs[(k + (lane & 15)) * LDB + wn + ni * 16 + 8 * (lane >> 4)]);
                asm volatile("ldmatrix.sync.aligned.m8n8.x4.trans.shared.b16 {%0,%1,%2,%3}, [%4];"
                             : "=r"(b[ni][0]), "=r"(b[ni][1]), "=r"(b[ni][2]), "=r"(b[ni][3])
                             : "r"(addr));
            }
            #pragma unroll
            for (int mi = 0; mi < 2; mi++)
                #pragma unroll
                for (int nj = 0; nj < 8; nj++) {
                    uint32_t b0 = b[nj >> 1][(nj & 1) * 2 + 0];
                    uint32_t b1 = b[nj >> 1][(nj & 1) * 2 + 1];
                    asm volatile(
                        "mma.sync.aligned.m16n8k16.row.col.f32.f16.f16.f32 "
                        "{%0,%1,%2,%3}, {%4,%5,%6,%7}, {%8,%9}, {%0,%1,%2,%3};"
                        : "+f"(acc[mi][nj][0]), "+f"(acc[mi][nj][1]),
                          "+f"(acc[mi][nj][2]), "+f"(acc[mi][nj][3])
                        : "r"(a[mi][0]), "r"(a[mi][1]), "r"(a[mi][2]), "r"(a[mi][3]),
                          "r"(b0), "r"(b1));
                }
        }
        __syncthreads();
    }
    // epilogue
    #pragma unroll
    for (int mi = 0; mi < 2; mi++)
        #pragma unroll
        for (int nj = 0; nj < 8; nj++) {
            int col = wn + nj * 8 + 2 * (lane & 3);
            float bx = 0.f, by = 0.f;
            if (LAYER1) { bx = bias[col]; by = bias[col + 1]; }
            #pragma unroll
            for (int h = 0; h < 2; h++) {
                int r = row0 + wm + mi * 16 + (lane >> 2) + h * 8;
                if (r < NN) {
                    float v0 = acc[mi][nj][2 * h + 0];
                    float v1 = acc[mi][nj][2 * h + 1];
                    if (LAYER1) {
                        v0 = fmaxf(v0 + bx, 0.f);
                        v1 = fmaxf(v1 + by, 0.f);
                    }
                    ((__half2*)out)[(r * 128 + col) >> 1] = __floats2half2_rn(v0, v1);
                }
            }
        }
}

// ---------------- layer-2 aggregation: a2 = relu(S @ h2 + b2), 128-dim ----------------
__global__ void __launch_bounds__(256) k_agg128(const float* __restrict__ bias) {
    int node = (blockIdx.x * 256 + threadIdx.x) >> 5;
    int lane = threadIdx.x & 31;
    if (node >= NN) return;
    float dn = g_dinv[node];
    float sl = dn * dn;
    uint2 sv = ((const uint2*)g_h2h)[node * 32 + lane];
    float2 s0 = __half22float2(*(__half2*)&sv.x);
    float2 s1 = __half22float2(*(__half2*)&sv.y);
    float4 acc = make_float4(s0.x * sl, s0.y * sl, s1.x * sl, s1.y * sl);
    int e   = g_rowptr[node];
    int end = g_rowptr[node + 1];
    #pragma unroll 4
    for (; e < end; e++) {
        int2 ed = __ldg(&g_edge[e]);
        float nm = __int_as_float(ed.y);
        uint2 hv = ((const uint2*)g_h2h)[ed.x * 32 + lane];
        float2 f0 = __half22float2(*(__half2*)&hv.x);
        float2 f1 = __half22float2(*(__half2*)&hv.y);
        acc.x += f0.x * nm; acc.y += f0.y * nm;
        acc.z += f1.x * nm; acc.w += f1.y * nm;
    }
    float4 b = ((const float4*)bias)[lane];
    acc.x = fmaxf(acc.x + b.x, 0.f);
    acc.y = fmaxf(acc.y + b.y, 0.f);
    acc.z = fmaxf(acc.z + b.z, 0.f);
    acc.w = fmaxf(acc.w + b.w, 0.f);
    ((float4*)g_a2)[node * 32 + lane] = acc;
}

// ---------------- fused pool (sorted batch -> contiguous ranges) + MLP head ----------------
__global__ void __launch_bounds__(128) k_poolmlp(const float* __restrict__ Wm1,
                                                 const float* __restrict__ bm1,
                                                 const float* __restrict__ Wm2,
                                                 const float* __restrict__ bm2,
                                                 float* __restrict__ out) {
    int g = blockIdx.x;
    int tid = threadIdx.x;
    __shared__ float ps[HID];
    __shared__ float zs[HID];
    int n0 = g_gptr[g], n1 = g_gptr[g + 1];
    float acc = 0.f;
    for (int n = n0; n < n1; n++)
        acc += g_a2[n * HID + tid];
    ps[tid] = acc;
    __syncthreads();
    float z = bm1[tid];
    #pragma unroll 8
    for (int k = 0; k < HID; k++) z += ps[k] * Wm1[k * HID + tid];
    zs[tid] = fmaxf(z, 0.f);
    __syncthreads();
    if (tid < OUTD) {
        float a = bm2[tid];
        #pragma unroll 8
        for (int k = 0; k < HID; k++) a += zs[k] * Wm2[k * OUTD + tid];
        out[g * OUTD + tid] = a;
    }
}

// ---------------- launch ----------------
extern "C" void kernel_launch(void* const* d_in, const int* in_sizes, int n_in,
                              void* d_out, int out_size) {
    const float* x   = (const float*)d_in[0];
    const void*  ei  = d_in[1];
    const void*  bt  = d_in[2];
    const float* ew  = (const float*)d_in[3];
    const float* W1  = (const float*)d_in[4];
    const float* b1  = (const float*)d_in[5];
    const float* W2  = (const float*)d_in[6];
    const float* b2  = (const float*)d_in[7];
    const float* Wm1 = (const float*)d_in[8];
    const float* bm1 = (const float*)d_in[9];
    const float* Wm2 = (const float*)d_in[10];
    const float* bm2 = (const float*)d_in[11];
    float* out = (float*)d_out;

    k_pre<<<(NN * IND / 2 + 255) / 256, 256>>>(x, W1, W2, (const unsigned*)ei);
    k_hist<<<(NE + 255) / 256, 256>>>(ei, bt, ew);
    k_dinv<<<(NN + 255) / 256, 256>>>();
    k_scanA<<<NBLK, SCAN_B>>>();
    k_scanB<<<1, 512>>>();
    k_scanC<<<NBLK, SCAN_B>>>();
    k_scatter<<<(NE + 255) / 256, 256>>>(ei, ew);
    k_aggx<<<(NN * 32 + 255) / 256, 256>>>(x);
    k_gemm16<true><<<(NN + 127) / 128, 256>>>(b1);
    k_gemm16<false><<<(NN + 127) / 128, 256>>>(nullptr);
    k_agg128<<<(NN * 32 + 255) / 256, 256>>>(b2);
    k_poolmlp<<<NG, 128>>>(Wm1, bm1, Wm2, bm2, out);
}

// round 6
// speedup vs baseline: 2.1376x; 1.0709x over previous
#include <cuda_runtime.h>
#include <cuda_fp16.h>
#include <cstdint>

#define NN   50000
#define NE   1600000
#define NG   512
#define IND  64
#define HID  128
#define OUTD 10
#define SCAN_B 1024
#define NBLK ((NN + SCAN_B - 1) / SCAN_B)   // 49

// ---------------- scratch (static __device__, zero-initialized; every kernel
// restores what it consumes so the graph can be replayed indefinitely) --------
__device__ int      g_is64;
__device__ float    g_deg[NN];        // starts 0; scanA resets after dinv
__device__ float    g_dinv[NN];
__device__ int      g_count[NN];      // starts 0; scanA resets
__device__ int      g_rowptr[NN + 1];
__device__ int      g_cursor[NN];
__device__ unsigned g_edge[NE];       // packed: src u16 | norm fp16 << 16
__device__ int      g_bsum[NBLK];
__device__ int      g_boff[NBLK];
__device__ int      g_gcount[NG];     // starts 0; scanB resets
__device__ int      g_gptr[NG + 1];
__device__ __half   g_xh[NN * IND];   // fp16 x for gather + self term
__device__ __half   g_w1h[IND * HID];
__device__ __half   g_w2h[HID * HID];
__device__ __half   g_axh[NN * IND];  // fp16 S @ x
__device__ __half   g_a1h[NN * HID];  // fp16 relu(axh @ W1 + b1)
__device__ __half   g_h2h[NN * HID];  // fp16 (a1 @ W2)
__device__ __half   g_a2h[NN * HID];  // fp16 relu(S @ h2 + b2)

// ---------------- dtype detect (must precede any index read) ----------------
__global__ void k_detect(const unsigned* __restrict__ ei_words) {
    if (threadIdx.x == 0) {
        int is64 = 1;
        #pragma unroll 1
        for (int k = 0; k < 128; k++)
            if (ei_words[2 * k + 1] != 0u) { is64 = 0; break; }
        g_is64 = is64;
    }
}

// ---------------- fused: histograms + fp16 conversions ----------------
__global__ void k_histpre(const void* __restrict__ ei, const void* __restrict__ batch,
                          const float* __restrict__ ew, const float* __restrict__ x,
                          const float* __restrict__ W1, const float* __restrict__ W2) {
    int i = blockIdx.x * blockDim.x + threadIdx.x;
    int is64 = g_is64;
    if (i < NE) {
        int d = is64 ? (int)((const long long*)ei)[NE + i] : ((const int*)ei)[NE + i];
        atomicAdd(&g_deg[d], ew[i]);
        atomicAdd(&g_count[d], 1);
    }
    if (i < NN) {
        int b = is64 ? (int)((const long long*)batch)[i] : ((const int*)batch)[i];
        atomicAdd(&g_gcount[b], 1);
    }
    if (i < NN * IND / 2) {
        float2 v = ((const float2*)x)[i];
        ((__half2*)g_xh)[i] = __floats2half2_rn(v.x, v.y);
    }
    if (i < IND * HID / 2) {
        float2 v = ((const float2*)W1)[i];
        ((__half2*)g_w1h)[i] = __floats2half2_rn(v.x, v.y);
    }
    if (i < HID * HID / 2) {
        float2 v = ((const float2*)W2)[i];
        ((__half2*)g_w2h)[i] = __floats2half2_rn(v.x, v.y);
    }
}

// ---------------- scanA: exclusive scan of counts (+ dinv, + restores) ----------------
__global__ void __launch_bounds__(SCAN_B) k_scanA() {
    __shared__ int ws[32];
    int tid = threadIdx.x, lane = tid & 31, warp = tid >> 5;
    int idx = blockIdx.x * SCAN_B + tid;
    int v = 0;
    if (idx < NN) {
        v = g_count[idx];
        g_count[idx] = 0;                           // restore
        g_dinv[idx] = rsqrtf(1.0f + g_deg[idx]);    // self-loop weight 1
        g_deg[idx] = 0.0f;                          // restore
    }
    int xi = v;
    #pragma unroll
    for (int off = 1; off < 32; off <<= 1) {
        int t = __shfl_up_sync(0xffffffffu, xi, off);
        if (lane >= off) xi += t;
    }
    if (lane == 31) ws[warp] = xi;
    __syncthreads();
    if (warp == 0) {
        int y = ws[lane];
        #pragma unroll
        for (int off = 1; off < 32; off <<= 1) {
            int t = __shfl_up_sync(0xffffffffu, y, off);
            if (lane >= off) y += t;
        }
        ws[lane] = y;
    }
    __syncthreads();
    int incl = xi + (warp ? ws[warp - 1] : 0);
    if (idx < NN) g_rowptr[idx] = incl - v;
    if (tid == SCAN_B - 1) g_bsum[blockIdx.x] = incl;
}

__global__ void __launch_bounds__(512) k_scanB() {
    __shared__ int ws[16];
    __shared__ int b[NBLK];
    int tid = threadIdx.x, lane = tid & 31, warp = tid >> 5;
    int gv = g_gcount[tid];
    g_gcount[tid] = 0;                              // restore
    int xi = gv;
    #pragma unroll
    for (int off = 1; off < 32; off <<= 1) {
        int t = __shfl_up_sync(0xffffffffu, xi, off);
        if (lane >= off) xi += t;
    }
    if (lane == 31) ws[warp] = xi;
    __syncthreads();
    if (warp == 0 && lane < 16) {
        int y = ws[lane];
        #pragma unroll
        for (int off = 1; off < 16; off <<= 1) {
            int t = __shfl_up_sync(0xffffu, y, off);
            if (lane >= off) y += t;
        }
        ws[lane] = y;
    }
    __syncthreads();
    g_gptr[tid] = xi + (warp ? ws[warp - 1] : 0) - gv;
    if (tid == 0) g_gptr[NG] = NN;
    if (tid < NBLK) b[tid] = g_bsum[tid];
    __syncthreads();
    if (tid == 0) {
        int run = 0;
        #pragma unroll 1
        for (int i = 0; i < NBLK; i++) { int v = b[i]; b[i] = run; run += v; }
    }
    __syncthreads();
    if (tid < NBLK) g_boff[tid] = b[tid];
}

__global__ void __launch_bounds__(SCAN_B) k_scanC() {
    int idx = blockIdx.x * SCAN_B + threadIdx.x;
    if (idx < NN) {
        int v = g_rowptr[idx] + g_boff[blockIdx.x];
        g_rowptr[idx] = v;
        g_cursor[idx] = v;
    }
    if (idx == 0) g_rowptr[NN] = NE;
}

// ---------------- scatter: packed (u16 src | fp16 norm) ----------------
__global__ void k_scatter(const void* __restrict__ ei, const float* __restrict__ ew) {
    int e = blockIdx.x * blockDim.x + threadIdx.x;
    if (e >= NE) return;
    int s, d;
    if (g_is64) {
        const long long* p = (const long long*)ei;
        s = (int)p[e]; d = (int)p[NE + e];
    } else {
        const int* p = (const int*)ei;
        s = p[e]; d = p[NE + e];
    }
    float nrm = g_dinv[s] * ew[e] * g_dinv[d];
    unsigned rec = (unsigned)s |
                   ((unsigned)__half_as_ushort(__float2half_rn(nrm)) << 16);
    int pos = atomicAdd(&g_cursor[d], 1);
    g_edge[pos] = rec;
}

// ---------------- layer-1 aggregation: axh = fp16(S @ x), 64-dim ----------------
__global__ void __launch_bounds__(256) k_aggx() {
    int node = (blockIdx.x * 256 + threadIdx.x) >> 5;
    int lane = threadIdx.x & 31;
    if (node >= NN) return;
    float dn = g_dinv[node];
    float sl = dn * dn;
    float2 self = __half22float2(((const __half2*)g_xh)[node * 32 + lane]);
    float2 acc = make_float2(self.x * sl, self.y * sl);
    int e   = g_rowptr[node];
    int end = g_rowptr[node + 1];
    #pragma unroll 4
    for (; e < end; e++) {
        unsigned rec = __ldg(&g_edge[e]);               // broadcast 4B
        int src  = rec & 0xFFFFu;
        float nm = __half2float(__ushort_as_half((unsigned short)(rec >> 16)));
        float2 hs = __half22float2(((const __half2*)g_xh)[src * 32 + lane]);
        acc.x += hs.x * nm; acc.y += hs.y * nm;
    }
    ((__half2*)g_axh)[node * 32 + lane] = __floats2half2_rn(acc.x, acc.y);
}

// ---------------- tensor-core GEMM over device globals ----------------
// LAYER1: g_a1h = relu(g_axh[NN,64] @ g_w1h + b1) ; else: g_h2h = g_a1h[NN,128] @ g_w2h
template<bool LAYER1>
__global__ void __launch_bounds__(256) k_gemm16(const float* __restrict__ bias) {
    constexpr int K   = LAYER1 ? IND : HID;
    constexpr int KC  = 64;
    constexpr int LDA = KC + 8;
    constexpr int LDB = 128 + 8;
    const __half* A = LAYER1 ? g_axh : g_a1h;
    const __half* W = LAYER1 ? g_w1h : g_w2h;
    __half* out     = LAYER1 ? g_a1h : g_h2h;
    __shared__ __half As[128 * LDA];
    __shared__ __half Bs[KC * LDB];
    int tid = threadIdx.x;
    int row0 = blockIdx.x * 128;
    int warp = tid >> 5, lane = tid & 31;
    int wm = (warp & 3) * 32;
    int wn = (warp >> 2) * 64;
    float acc[2][8][4];
    #pragma unroll
    for (int mi = 0; mi < 2; mi++)
        #pragma unroll
        for (int nj = 0; nj < 8; nj++)
            #pragma unroll
            for (int q = 0; q < 4; q++) acc[mi][nj][q] = 0.f;

    for (int kc = 0; kc < K; kc += KC) {
        for (int i = tid; i < 128 * KC / 8; i += 256) {
            int r = i >> 3, c = (i & 7) * 8;
            uint4 v = make_uint4(0u, 0u, 0u, 0u);
            if (row0 + r < NN)
                v = ((const uint4*)A)[(row0 + r) * (K / 8) + (kc + c) / 8];
            *(uint4*)&As[r * LDA + c] = v;
        }
        for (int i = tid; i < KC * 128 / 8; i += 256) {
            int r = i >> 4, c = (i & 15) * 8;
            *(uint4*)&Bs[r * LDB + c] = ((const uint4*)W)[((kc + r) * 128 + c) / 8];
        }
        __syncthreads();
        #pragma unroll
        for (int k = 0; k < KC; k += 16) {
            uint32_t a[2][4], b[4][4];
            #pragma unroll
            for (int mi = 0; mi < 2; mi++) {
                uint32_t addr = (uint32_t)__cvta_generic_to_shared(
                    &As[(wm + mi * 16 + (lane & 15)) * LDA + k + 8 * (lane >> 4)]);
                asm volatile("ldmatrix.sync.aligned.m8n8.x4.shared.b16 {%0,%1,%2,%3}, [%4];"
                             : "=r"(a[mi][0]), "=r"(a[mi][1]), "=r"(a[mi][2]), "=r"(a[mi][3])
                             : "r"(addr));
            }
            #pragma unroll
            for (int ni = 0; ni < 4; ni++) {
                uint32_t addr = (uint32_t)__cvta_generic_to_shared(
                    &Bs[(k + (lane & 15)) * LDB + wn + ni * 16 + 8 * (lane >> 4)]);
                asm volatile("ldmatrix.sync.aligned.m8n8.x4.trans.shared.b16 {%0,%1,%2,%3}, [%4];"
                             : "=r"(b[ni][0]), "=r"(b[ni][1]), "=r"(b[ni][2]), "=r"(b[ni][3])
                             : "r"(addr));
            }
            #pragma unroll
            for (int mi = 0; mi < 2; mi++)
                #pragma unroll
                for (int nj = 0; nj < 8; nj++) {
                    uint32_t b0 = b[nj >> 1][(nj & 1) * 2 + 0];
                    uint32_t b1 = b[nj >> 1][(nj & 1) * 2 + 1];
                    asm volatile(
                        "mma.sync.aligned.m16n8k16.row.col.f32.f16.f16.f32 "
                        "{%0,%1,%2,%3}, {%4,%5,%6,%7}, {%8,%9}, {%0,%1,%2,%3};"
                        : "+f"(acc[mi][nj][0]), "+f"(acc[mi][nj][1]),
                          "+f"(acc[mi][nj][2]), "+f"(acc[mi][nj][3])
                        : "r"(a[mi][0]), "r"(a[mi][1]), "r"(a[mi][2]), "r"(a[mi][3]),
                          "r"(b0), "r"(b1));
                }
        }
        __syncthreads();
    }
    #pragma unroll
    for (int mi = 0; mi < 2; mi++)
        #pragma unroll
        for (int nj = 0; nj < 8; nj++) {
            int col = wn + nj * 8 + 2 * (lane & 3);
            float bx = 0.f, by = 0.f;
            if (LAYER1) { bx = bias[col]; by = bias[col + 1]; }
            #pragma unroll
            for (int h = 0; h < 2; h++) {
                int r = row0 + wm + mi * 16 + (lane >> 2) + h * 8;
                if (r < NN) {
                    float v0 = acc[mi][nj][2 * h + 0];
                    float v1 = acc[mi][nj][2 * h + 1];
                    if (LAYER1) {
                        v0 = fmaxf(v0 + bx, 0.f);
                        v1 = fmaxf(v1 + by, 0.f);
                    }
                    ((__half2*)out)[(r * 128 + col) >> 1] = __floats2half2_rn(v0, v1);
                }
            }
        }
}

// ---------------- layer-2 aggregation: a2h = fp16(relu(S @ h2 + b2)), 128-dim ----------------
__global__ void __launch_bounds__(256) k_agg128(const float* __restrict__ bias) {
    int node = (blockIdx.x * 256 + threadIdx.x) >> 5;
    int lane = threadIdx.x & 31;
    if (node >= NN) return;
    float dn = g_dinv[node];
    float sl = dn * dn;
    uint2 sv = ((const uint2*)g_h2h)[node * 32 + lane];
    float2 s0 = __half22float2(*(__half2*)&sv.x);
    float2 s1 = __half22float2(*(__half2*)&sv.y);
    float4 acc = make_float4(s0.x * sl, s0.y * sl, s1.x * sl, s1.y * sl);
    int e   = g_rowptr[node];
    int end = g_rowptr[node + 1];
    #pragma unroll 4
    for (; e < end; e++) {
        unsigned rec = __ldg(&g_edge[e]);
        int src  = rec & 0xFFFFu;
        float nm = __half2float(__ushort_as_half((unsigned short)(rec >> 16)));
        uint2 hv = ((const uint2*)g_h2h)[src * 32 + lane];
        float2 f0 = __half22float2(*(__half2*)&hv.x);
        float2 f1 = __half22float2(*(__half2*)&hv.y);
        acc.x += f0.x * nm; acc.y += f0.y * nm;
        acc.z += f1.x * nm; acc.w += f1.y * nm;
    }
    float4 b = ((const float4*)bias)[lane];
    acc.x = fmaxf(acc.x + b.x, 0.f);
    acc.y = fmaxf(acc.y + b.y, 0.f);
    acc.z = fmaxf(acc.z + b.z, 0.f);
    acc.w = fmaxf(acc.w + b.w, 0.f);
    uint2 pk;
    __half2 h0 = __floats2half2_rn(acc.x, acc.y);
    __half2 h1 = __floats2half2_rn(acc.z, acc.w);
    pk.x = *(unsigned*)&h0;
    pk.y = *(unsigned*)&h1;
    ((uint2*)g_a2h)[node * 32 + lane] = pk;
}

// ---------------- fused pool (sorted batch -> contiguous ranges) + MLP head ----------------
__global__ void __launch_bounds__(128) k_poolmlp(const float* __restrict__ Wm1,
                                                 const float* __restrict__ bm1,
                                                 const float* __restrict__ Wm2,
                                                 const float* __restrict__ bm2,
                                                 float* __restrict__ out) {
    int g = blockIdx.x;
    int tid = threadIdx.x;
    __shared__ float ps[HID];
    __shared__ float zs[HID];
    int n0 = g_gptr[g], n1 = g_gptr[g + 1];
    float acc = 0.f;
    for (int n = n0; n < n1; n++)
        acc += __half2float(g_a2h[n * HID + tid]);
    ps[tid] = acc;
    __syncthreads();
    float z = bm1[tid];
    #pragma unroll 8
    for (int k = 0; k < HID; k++) z += ps[k] * Wm1[k * HID + tid];
    zs[tid] = fmaxf(z, 0.f);
    __syncthreads();
    if (tid < OUTD) {
        float a = bm2[tid];
        #pragma unroll 8
        for (int k = 0; k < HID; k++) a += zs[k] * Wm2[k * OUTD + tid];
        out[g * OUTD + tid] = a;
    }
}

// ---------------- launch ----------------
extern "C" void kernel_launch(void* const* d_in, const int* in_sizes, int n_in,
                              void* d_out, int out_size) {
    const float* x   = (const float*)d_in[0];
    const void*  ei  = d_in[1];
    const void*  bt  = d_in[2];
    const float* ew  = (const float*)d_in[3];
    const float* W1  = (const float*)d_in[4];
    const float* b1  = (const float*)d_in[5];
    const float* W2  = (const float*)d_in[6];
    const float* b2  = (const float*)d_in[7];
    const float* Wm1 = (const float*)d_in[8];
    const float* bm1 = (const float*)d_in[9];
    const float* Wm2 = (const float*)d_in[10];
    const float* bm2 = (const float*)d_in[11];
    float* out = (float*)d_out;

    k_detect<<<1, 32>>>((const unsigned*)ei);
    k_histpre<<<(NE + 255) / 256, 256>>>(ei, bt, ew, x, W1, W2);
    k_scanA<<<NBLK, SCAN_B>>>();
    k_scanB<<<1, 512>>>();
    k_scanC<<<NBLK, SCAN_B>>>();
    k_scatter<<<(NE + 255) / 256, 256>>>(ei, ew);
    k_aggx<<<(NN * 32 + 255) / 256, 256>>>();
    k_gemm16<true><<<(NN + 127) / 128, 256>>>(b1);
    k_gemm16<false><<<(NN + 127) / 128, 256>>>(nullptr);
    k_agg128<<<(NN * 32 + 255) / 256, 256>>>(b2);
    k_poolmlp<<<NG, 128>>>(Wm1, bm1, Wm2, bm2, out);
}

// round 7
// speedup vs baseline: 2.1556x; 1.0084x over previous
#include <cuda_runtime.h>
#include <cuda_fp16.h>
#include <cstdint>

#define NN   50000
#define NE   1600000
#define NG   512
#define IND  64
#define HID  128
#define OUTD 10
#define SCAN_B 1024
#define NBLK ((NN + SCAN_B - 1) / SCAN_B)   // 49
#define FLAG_AGG (1 << 30)
#define FLAG_INC (2 << 30)
#define VAL_MASK ((1 << 30) - 1)
#define FULL 0xffffffffu

// ---------------- scratch (static __device__, zero-initialized; every kernel
// restores what it consumes so the graph can be replayed indefinitely) --------
__device__ int      g_is64;
__device__ float    g_deg[NN];        // starts 0; scan resets after dinv
__device__ float    g_dinv[NN];
__device__ int      g_count[NN];      // starts 0; scan resets
__device__ int      g_rowptr[NN + 1];
__device__ int      g_cursor[NN];
__device__ unsigned g_edge[NE];       // packed: src u16 | norm fp16 << 16
__device__ int      g_desc[NBLK];     // lookback descriptors; last block resets
__device__ int      g_done;           // ticket counter; last block resets
__device__ int      g_gcount[NG];     // starts 0; scan resets
__device__ int      g_gptr[NG + 1];
__device__ __half   g_xh[NN * IND];   // fp16 x for gather + self term
__device__ __half   g_w1h[IND * HID];
__device__ __half   g_w2h[HID * HID];
__device__ __half   g_axh[NN * IND];  // fp16 S @ x
__device__ __half   g_a1h[NN * HID];  // fp16 relu(axh @ W1 + b1)
__device__ __half   g_h2h[NN * HID];  // fp16 (a1 @ W2)
__device__ __half   g_a2h[NN * HID];  // fp16 relu(S @ h2 + b2)

// ---------------- dtype detect (parallel; must precede any index read) -------
__global__ void k_detect(const unsigned* __restrict__ ei_words) {
    __shared__ int flag;
    int t = threadIdx.x;             // 128 threads
    if (t == 0) flag = 1;
    __syncthreads();
    if (ei_words[2 * t + 1] != 0u) flag = 0;   // benign race (all write 0)
    __syncthreads();
    if (t == 0) g_is64 = flag;
}

// ---------------- fused: histograms + fp16 conversions ----------------
__global__ void k_histpre(const void* __restrict__ ei, const void* __restrict__ batch,
                          const float* __restrict__ ew, const float* __restrict__ x,
                          const float* __restrict__ W1, const float* __restrict__ W2) {
    int i = blockIdx.x * blockDim.x + threadIdx.x;
    int is64 = g_is64;
    if (i < NE) {
        int d = is64 ? (int)((const long long*)ei)[NE + i] : ((const int*)ei)[NE + i];
        atomicAdd(&g_deg[d], ew[i]);
        atomicAdd(&g_count[d], 1);
    }
    if (i < NN) {
        int b = is64 ? (int)((const long long*)batch)[i] : ((const int*)batch)[i];
        atomicAdd(&g_gcount[b], 1);
    }
    if (i < NN * IND / 2) {
        float2 v = ((const float2*)x)[i];
        ((__half2*)g_xh)[i] = __floats2half2_rn(v.x, v.y);
    }
    if (i < IND * HID / 2) {
        float2 v = ((const float2*)W1)[i];
        ((__half2*)g_w1h)[i] = __floats2half2_rn(v.x, v.y);
    }
    if (i < HID * HID / 2) {
        float2 v = ((const float2*)W2)[i];
        ((__half2*)g_w2h)[i] = __floats2half2_rn(v.x, v.y);
    }
}

// ---------------- single-pass scan: counts->rowptr/cursor, dinv, gptr --------
__global__ void __launch_bounds__(SCAN_B) k_scan() {
    __shared__ int ws[32];
    __shared__ int ws2[16];
    __shared__ int s_excl;
    int tid = threadIdx.x, lane = tid & 31, warp = tid >> 5;
    int b = blockIdx.x;
    int idx = b * SCAN_B + tid;
    int v = 0;
    if (idx < NN) {
        v = g_count[idx];
        g_count[idx] = 0;                           // restore
        g_dinv[idx] = rsqrtf(1.0f + g_deg[idx]);    // self-loop weight 1
        g_deg[idx] = 0.0f;                          // restore
    }
    // block-local inclusive scan
    int xi = v;
    #pragma unroll
    for (int off = 1; off < 32; off <<= 1) {
        int t = __shfl_up_sync(FULL, xi, off);
        if (lane >= off) xi += t;
    }
    if (lane == 31) ws[warp] = xi;
    __syncthreads();
    if (warp == 0) {
        int y = ws[lane];
        #pragma unroll
        for (int off = 1; off < 32; off <<= 1) {
            int t = __shfl_up_sync(FULL, y, off);
            if (lane >= off) y += t;
        }
        ws[lane] = y;
        int total = __shfl_sync(FULL, y, 31);
        // publish aggregate ASAP
        if (lane == 0) {
            *((volatile int*)&g_desc[b]) = FLAG_AGG | total;
            __threadfence();
        }
        // decoupled lookback
        int excl = 0;
        if (b > 0) {
            int p = b - 1;
            for (;;) {
                int j = p - lane;
                int d;
                do {
                    d = (j >= 0) ? *((volatile int*)&g_desc[j]) : FLAG_INC;
                } while (__any_sync(FULL, d == 0));
                unsigned incmask = __ballot_sync(FULL, (d & FLAG_INC) != 0);
                if (incmask) {
                    int fi = __ffs(incmask) - 1;   // most recent inclusive
                    int c = (lane <= fi) ? (d & VAL_MASK) : 0;
                    #pragma unroll
                    for (int off = 16; off > 0; off >>= 1)
                        c += __shfl_down_sync(FULL, c, off);
                    excl += __shfl_sync(FULL, c, 0);
                    break;
                } else {
                    int c = d & VAL_MASK;
                    #pragma unroll
                    for (int off = 16; off > 0; off >>= 1)
                        c += __shfl_down_sync(FULL, c, off);
                    excl += __shfl_sync(FULL, c, 0);
                    p -= 32;
                }
            }
        }
        if (lane == 0) {
            *((volatile int*)&g_desc[b]) = FLAG_INC | (excl + total);
            __threadfence();
            s_excl = excl;
        }
    }
    __syncthreads();
    int excl = s_excl;
    int incl = xi + (warp ? ws[warp - 1] : 0);
    if (idx < NN) {
        int r = excl + incl - v;
        g_rowptr[idx] = r;
        g_cursor[idx] = r;
    }
    if (b == 0 && tid == 0) g_rowptr[NN] = NE;

    // ---- block 0: gptr scan over NG=512 bins ----
    int gv = 0;
    if (b == 0 && tid < NG) { gv = g_gcount[tid]; g_gcount[tid] = 0; }
    int x2 = gv;
    #pragma unroll
    for (int off = 1; off < 32; off <<= 1) {
        int t = __shfl_up_sync(FULL, x2, off);
        if (lane >= off) x2 += t;
    }
    if (b == 0 && tid < NG && lane == 31) ws2[warp] = x2;
    __syncthreads();
    if (b == 0 && warp == 0 && lane < 16) {
        int y = ws2[lane];
        #pragma unroll
        for (int off = 1; off < 16; off <<= 1) {
            int t = __shfl_up_sync(0xffffu, y, off);
            if (lane >= off) y += t;
        }
        ws2[lane] = y;
    }
    __syncthreads();
    if (b == 0 && tid < NG)
        g_gptr[tid] = x2 + (warp ? ws2[warp - 1] : 0) - gv;
    if (b == 0 && tid == 0) g_gptr[NG] = NN;

    // ---- cleanup: last block to finish resets descriptors for next replay ----
    __syncthreads();
    if (tid == 0) {
        int t = atomicAdd(&g_done, 1);
        if (t == NBLK - 1) {
            #pragma unroll 1
            for (int i = 0; i < NBLK; i++) g_desc[i] = 0;
            g_done = 0;
            __threadfence();
        }
    }
}

// ---------------- scatter: packed (u16 src | fp16 norm) ----------------
__global__ void k_scatter(const void* __restrict__ ei, const float* __restrict__ ew) {
    int e = blockIdx.x * blockDim.x + threadIdx.x;
    if (e >= NE) return;
    int s, d;
    if (g_is64) {
        const long long* p = (const long long*)ei;
        s = (int)p[e]; d = (int)p[NE + e];
    } else {
        const int* p = (const int*)ei;
        s = p[e]; d = p[NE + e];
    }
    float nrm = g_dinv[s] * ew[e] * g_dinv[d];
    unsigned rec = (unsigned)s |
                   ((unsigned)__half_as_ushort(__float2half_rn(nrm)) << 16);
    int pos = atomicAdd(&g_cursor[d], 1);
    g_edge[pos] = rec;
}

// ---------------- layer-1 aggregation: axh = fp16(S @ x), 64-dim ----------------
__global__ void __launch_bounds__(256) k_aggx() {
    int node = (blockIdx.x * 256 + threadIdx.x) >> 5;
    int lane = threadIdx.x & 31;
    if (node >= NN) return;
    float dn = g_dinv[node];
    float sl = dn * dn;
    float2 self = __half22float2(((const __half2*)g_xh)[node * 32 + lane]);
    float2 acc = make_float2(self.x * sl, self.y * sl);
    int e   = g_rowptr[node];
    int end = g_rowptr[node + 1];
    #pragma unroll 4
    for (; e < end; e++) {
        unsigned rec = __ldg(&g_edge[e]);
        int src  = rec & 0xFFFFu;
        float nm = __half2float(__ushort_as_half((unsigned short)(rec >> 16)));
        float2 hs = __half22float2(((const __half2*)g_xh)[src * 32 + lane]);
        acc.x += hs.x * nm; acc.y += hs.y * nm;
    }
    ((__half2*)g_axh)[node * 32 + lane] = __floats2half2_rn(acc.x, acc.y);
}

// ---------------- tensor-core GEMM over device globals ----------------
template<bool LAYER1>
__global__ void __launch_bounds__(256) k_gemm16(const float* __restrict__ bias) {
    constexpr int K   = LAYER1 ? IND : HID;
    constexpr int KC  = 64;
    constexpr int LDA = KC + 8;
    constexpr int LDB = 128 + 8;
    const __half* A = LAYER1 ? g_axh : g_a1h;
    const __half* W = LAYER1 ? g_w1h : g_w2h;
    __half* out     = LAYER1 ? g_a1h : g_h2h;
    __shared__ __half As[128 * LDA];
    __shared__ __half Bs[KC * LDB];
    int tid = threadIdx.x;
    int row0 = blockIdx.x * 128;
    int warp = tid >> 5, lane = tid & 31;
    int wm = (warp & 3) * 32;
    int wn = (warp >> 2) * 64;
    float acc[2][8][4];
    #pragma unroll
    for (int mi = 0; mi < 2; mi++)
        #pragma unroll
        for (int nj = 0; nj < 8; nj++)
            #pragma unroll
            for (int q = 0; q < 4; q++) acc[mi][nj][q] = 0.f;

    for (int kc = 0; kc < K; kc += KC) {
        for (int i = tid; i < 128 * KC / 8; i += 256) {
            int r = i >> 3, c = (i & 7) * 8;
            uint4 v = make_uint4(0u, 0u, 0u, 0u);
            if (row0 + r < NN)
                v = ((const uint4*)A)[(row0 + r) * (K / 8) + (kc + c) / 8];
            *(uint4*)&As[r * LDA + c] = v;
        }
        for (int i = tid; i < KC * 128 / 8; i += 256) {
            int r = i >> 4, c = (i & 15) * 8;
            *(uint4*)&Bs[r * LDB + c] = ((const uint4*)W)[((kc + r) * 128 + c) / 8];
        }
        __syncthreads();
        #pragma unroll
        for (int k = 0; k < KC; k += 16) {
            uint32_t a[2][4], b[4][4];
            #pragma unroll
            for (int mi = 0; mi < 2; mi++) {
                uint32_t addr = (uint32_t)__cvta_generic_to_shared(
                    &As[(wm + mi * 16 + (lane & 15)) * LDA + k + 8 * (lane >> 4)]);
                asm volatile("ldmatrix.sync.aligned.m8n8.x4.shared.b16 {%0,%1,%2,%3}, [%4];"
                             : "=r"(a[mi][0]), "=r"(a[mi][1]), "=r"(a[mi][2]), "=r"(a[mi][3])
                             : "r"(addr));
            }
            #pragma unroll
            for (int ni = 0; ni < 4; ni++) {
                uint32_t addr = (uint32_t)__cvta_generic_to_shared(
                    &Bs[(k + (lane & 15)) * LDB + wn + ni * 16 + 8 * (lane >> 4)]);
                asm volatile("ldmatrix.sync.aligned.m8n8.x4.trans.shared.b16 {%0,%1,%2,%3}, [%4];"
                             : "=r"(b[ni][0]), "=r"(b[ni][1]), "=r"(b[ni][2]), "=r"(b[ni][3])
                             : "r"(addr));
            }
            #pragma unroll
            for (int mi = 0; mi < 2; mi++)
                #pragma unroll
                for (int nj = 0; nj < 8; nj++) {
                    uint32_t b0 = b[nj >> 1][(nj & 1) * 2 + 0];
                    uint32_t b1 = b[nj >> 1][(nj & 1) * 2 + 1];
                    asm volatile(
                        "mma.sync.aligned.m16n8k16.row.col.f32.f16.f16.f32 "
                        "{%0,%1,%2,%3}, {%4,%5,%6,%7}, {%8,%9}, {%0,%1,%2,%3};"
                        : "+f"(acc[mi][nj][0]), "+f"(acc[mi][nj][1]),
                          "+f"(acc[mi][nj][2]), "+f"(acc[mi][nj][3])
                        : "r"(a[mi][0]), "r"(a[mi][1]), "r"(a[mi][2]), "r"(a[mi][3]),
                          "r"(b0), "r"(b1));
                }
        }
        __syncthreads();
    }
    #pragma unroll
    for (int mi = 0; mi < 2; mi++)
        #pragma unroll
        for (int nj = 0; nj < 8; nj++) {
            int col = wn + nj * 8 + 2 * (lane & 3);
            float bx = 0.f, by = 0.f;
            if (LAYER1) { bx = bias[col]; by = bias[col + 1]; }
            #pragma unroll
            for (int h = 0; h < 2; h++) {
                int r = row0 + wm + mi * 16 + (lane >> 2) + h * 8;
                if (r < NN) {
                    float v0 = acc[mi][nj][2 * h + 0];
                    float v1 = acc[mi][nj][2 * h + 1];
                    if (LAYER1) {
                        v0 = fmaxf(v0 + bx, 0.f);
                        v1 = fmaxf(v1 + by, 0.f);
                    }
                    ((__half2*)out)[(r * 128 + col) >> 1] = __floats2half2_rn(v0, v1);
                }
            }
        }
}

// ---------------- layer-2 aggregation: a2h = fp16(relu(S @ h2 + b2)) ----------------
__global__ void __launch_bounds__(256) k_agg128(const float* __restrict__ bias) {
    int node = (blockIdx.x * 256 + threadIdx.x) >> 5;
    int lane = threadIdx.x & 31;
    if (node >= NN) return;
    float dn = g_dinv[node];
    float sl = dn * dn;
    uint2 sv = ((const uint2*)g_h2h)[node * 32 + lane];
    float2 s0 = __half22float2(*(__half2*)&sv.x);
    float2 s1 = __half22float2(*(__half2*)&sv.y);
    float4 acc = make_float4(s0.x * sl, s0.y * sl, s1.x * sl, s1.y * sl);
    int e   = g_rowptr[node];
    int end = g_rowptr[node + 1];
    #pragma unroll 4
    for (; e < end; e++) {
        unsigned rec = __ldg(&g_edge[e]);
        int src  = rec & 0xFFFFu;
        float nm = __half2float(__ushort_as_half((unsigned short)(rec >> 16)));
        uint2 hv = ((const uint2*)g_h2h)[src * 32 + lane];
        float2 f0 = __half22float2(*(__half2*)&hv.x);
        float2 f1 = __half22float2(*(__half2*)&hv.y);
        acc.x += f0.x * nm; acc.y += f0.y * nm;
        acc.z += f1.x * nm; acc.w += f1.y * nm;
    }
    float4 b = ((const float4*)bias)[lane];
    acc.x = fmaxf(acc.x + b.x, 0.f);
    acc.y = fmaxf(acc.y + b.y, 0.f);
    acc.z = fmaxf(acc.z + b.z, 0.f);
    acc.w = fmaxf(acc.w + b.w, 0.f);
    uint2 pk;
    __half2 h0 = __floats2half2_rn(acc.x, acc.y);
    __half2 h1 = __floats2half2_rn(acc.z, acc.w);
    pk.x = *(unsigned*)&h0;
    pk.y = *(unsigned*)&h1;
    ((uint2*)g_a2h)[node * 32 + lane] = pk;
}

// ---------------- fused pool (sorted batch -> contiguous ranges) + MLP head ----------------
__global__ void __launch_bounds__(128) k_poolmlp(const float* __restrict__ Wm1,
                                                 const float* __restrict__ bm1,
                                                 const float* __restrict__ Wm2,
                                                 const float* __restrict__ bm2,
                                                 float* __restrict__ out) {
    int g = blockIdx.x;
    int tid = threadIdx.x;
    __shared__ float ps[HID];
    __shared__ float zs[HID];
    int n0 = g_gptr[g], n1 = g_gptr[g + 1];
    float acc = 0.f;
    for (int n = n0; n < n1; n++)
        acc += __half2float(g_a2h[n * HID + tid]);
    ps[tid] = acc;
    __syncthreads();
    float z = bm1[tid];
    #pragma unroll 8
    for (int k = 0; k < HID; k++) z += ps[k] * Wm1[k * HID + tid];
    zs[tid] = fmaxf(z, 0.f);
    __syncthreads();
    if (tid < OUTD) {
        float a = bm2[tid];
        #pragma unroll 8
        for (int k = 0; k < HID; k++) a += zs[k] * Wm2[k * OUTD + tid];
        out[g * OUTD + tid] = a;
    }
}

// ---------------- launch ----------------
extern "C" void kernel_launch(void* const* d_in, const int* in_sizes, int n_in,
                              void* d_out, int out_size) {
    const float* x   = (const float*)d_in[0];
    const void*  ei  = d_in[1];
    const void*  bt  = d_in[2];
    const float* ew  = (const float*)d_in[3];
    const float* W1  = (const float*)d_in[4];
    const float* b1  = (const float*)d_in[5];
    const float* W2  = (const float*)d_in[6];
    const float* b2  = (const float*)d_in[7];
    const float* Wm1 = (const float*)d_in[8];
    const float* bm1 = (const float*)d_in[9];
    const float* Wm2 = (const float*)d_in[10];
    const float* bm2 = (const float*)d_in[11];
    float* out = (float*)d_out;

    k_detect<<<1, 128>>>((const unsigned*)ei);
    k_histpre<<<(NE + 255) / 256, 256>>>(ei, bt, ew, x, W1, W2);
    k_scan<<<NBLK, SCAN_B>>>();
    k_scatter<<<(NE + 255) / 256, 256>>>(ei, ew);
    k_aggx<<<(NN * 32 + 255) / 256, 256>>>();
    k_gemm16<true><<<(NN + 127) / 128, 256>>>(b1);
    k_gemm16<false><<<(NN + 127) / 128, 256>>>(nullptr);
    k_agg128<<<(NN * 32 + 255) / 256, 256>>>(b2);
    k_poolmlp<<<NG, 128>>>(Wm1, bm1, Wm2, bm2, out);
}

// round 8
// speedup vs baseline: 2.2812x; 1.0583x over previous
#include <cuda_runtime.h>
#include <cuda_fp16.h>
#include <cstdint>

#define NN   50000
#define NE   1600000
#define NG   512
#define IND  64
#define HID  128
#define OUTD 10
#define SCAN_B 1024
#define NBLK ((NN + SCAN_B - 1) / SCAN_B)   // 49
#define FLAG_AGG (1 << 30)
#define FLAG_INC (2 << 30)
#define VAL_MASK ((1 << 30) - 1)
#define FULL 0xffffffffu

// ---------------- scratch (static __device__, zero-initialized; every kernel
// restores what it consumes so the graph can be replayed indefinitely) --------
__device__ int            g_is64;
__device__ float          g_deg[NN];     // starts 0; scan resets after dinv
__device__ float          g_dinv[NN];
__device__ int            g_count[NN];   // starts 0; scan resets
__device__ int            g_rowptr[NN + 1];
__device__ unsigned short g_rank[NE];    // edge rank within dst bucket
__device__ unsigned       g_edge[NE];    // packed: src u16 | ew fp16 << 16
__device__ int            g_desc[NBLK];  // lookback descriptors; last block resets
__device__ int            g_done;        // ticket counter; last block resets
__device__ int            g_gcount[NG];  // starts 0; scan resets
__device__ int            g_gptr[NG + 1];
__device__ __half         g_xh[NN * IND];   // fp16 x; scaled by dinv[row] in scatter
__device__ __half         g_w1h[IND * HID];
__device__ __half         g_w2h[HID * HID];
__device__ __half         g_axh[NN * IND];  // fp16 (S@x) pre-scaled view input
__device__ __half         g_h2h[NN * HID];  // fp16 dinv[row]*(a1 @ W2)
__device__ __half         g_a2h[NN * HID];  // fp16 relu(S @ h2 + b2)

// ---------------- dtype detect (parallel; must precede any index read) -------
__global__ void k_detect(const unsigned* __restrict__ ei_words) {
    __shared__ int flag;
    int t = threadIdx.x;             // 128 threads
    if (t == 0) flag = 1;
    __syncthreads();
    if (ei_words[2 * t + 1] != 0u) flag = 0;   // benign race (all write 0)
    __syncthreads();
    if (t == 0) g_is64 = flag;
}

// ---------------- fused: histograms (+edge rank) + fp16 conversions ----------
__global__ void k_histpre(const void* __restrict__ ei, const void* __restrict__ batch,
                          const float* __restrict__ ew, const float* __restrict__ x,
                          const float* __restrict__ W1, const float* __restrict__ W2) {
    int i = blockIdx.x * blockDim.x + threadIdx.x;
    int is64 = g_is64;
    if (i < NE) {
        int d = is64 ? (int)((const long long*)ei)[NE + i] : ((const int*)ei)[NE + i];
        atomicAdd(&g_deg[d], ew[i]);
        g_rank[i] = (unsigned short)atomicAdd(&g_count[d], 1);
    }
    if (i < NN) {
        int b = is64 ? (int)((const long long*)batch)[i] : ((const int*)batch)[i];
        atomicAdd(&g_gcount[b], 1);
    }
    if (i < NN * IND / 2) {
        float2 v = ((const float2*)x)[i];
        ((__half2*)g_xh)[i] = __floats2half2_rn(v.x, v.y);
    }
    if (i < IND * HID / 2) {
        float2 v = ((const float2*)W1)[i];
        ((__half2*)g_w1h)[i] = __floats2half2_rn(v.x, v.y);
    }
    if (i < HID * HID / 2) {
        float2 v = ((const float2*)W2)[i];
        ((__half2*)g_w2h)[i] = __floats2half2_rn(v.x, v.y);
    }
}

// ---------------- single-pass scan: counts->rowptr, dinv, gptr --------------
__global__ void __launch_bounds__(SCAN_B) k_scan() {
    __shared__ int ws[32];
    __shared__ int ws2[16];
    __shared__ int s_excl;
    int tid = threadIdx.x, lane = tid & 31, warp = tid >> 5;
    int b = blockIdx.x;
    int idx = b * SCAN_B + tid;
    int v = 0;
    if (idx < NN) {
        v = g_count[idx];
        g_count[idx] = 0;                           // restore
        g_dinv[idx] = rsqrtf(1.0f + g_deg[idx]);    // self-loop weight 1
        g_deg[idx] = 0.0f;                          // restore
    }
    int xi = v;
    #pragma unroll
    for (int off = 1; off < 32; off <<= 1) {
        int t = __shfl_up_sync(FULL, xi, off);
        if (lane >= off) xi += t;
    }
    if (lane == 31) ws[warp] = xi;
    __syncthreads();
    if (warp == 0) {
        int y = ws[lane];
        #pragma unroll
        for (int off = 1; off < 32; off <<= 1) {
            int t = __shfl_up_sync(FULL, y, off);
            if (lane >= off) y += t;
        }
        ws[lane] = y;
        int total = __shfl_sync(FULL, y, 31);
        if (lane == 0) {
            *((volatile int*)&g_desc[b]) = FLAG_AGG | total;
            __threadfence();
        }
        int excl = 0;
        if (b > 0) {
            int p = b - 1;
            for (;;) {
                int j = p - lane;
                int d;
                do {
                    d = (j >= 0) ? *((volatile int*)&g_desc[j]) : FLAG_INC;
                } while (__any_sync(FULL, d == 0));
                unsigned incmask = __ballot_sync(FULL, (d & FLAG_INC) != 0);
                if (incmask) {
                    int fi = __ffs(incmask) - 1;
                    int c = (lane <= fi) ? (d & VAL_MASK) : 0;
                    #pragma unroll
                    for (int off = 16; off > 0; off >>= 1)
                        c += __shfl_down_sync(FULL, c, off);
                    excl += __shfl_sync(FULL, c, 0);
                    break;
                } else {
                    int c = d & VAL_MASK;
                    #pragma unroll
                    for (int off = 16; off > 0; off >>= 1)
                        c += __shfl_down_sync(FULL, c, off);
                    excl += __shfl_sync(FULL, c, 0);
                    p -= 32;
                }
            }
        }
        if (lane == 0) {
            *((volatile int*)&g_desc[b]) = FLAG_INC | (excl + total);
            __threadfence();
            s_excl = excl;
        }
    }
    __syncthreads();
    int excl = s_excl;
    int incl = xi + (warp ? ws[warp - 1] : 0);
    if (idx < NN) g_rowptr[idx] = excl + incl - v;
    if (b == 0 && tid == 0) g_rowptr[NN] = NE;

    // block 0: gptr scan over NG=512 bins
    int gv = 0;
    if (b == 0 && tid < NG) { gv = g_gcount[tid]; g_gcount[tid] = 0; }
    int x2 = gv;
    #pragma unroll
    for (int off = 1; off < 32; off <<= 1) {
        int t = __shfl_up_sync(FULL, x2, off);
        if (lane >= off) x2 += t;
    }
    if (b == 0 && tid < NG && lane == 31) ws2[warp] = x2;
    __syncthreads();
    if (b == 0 && warp == 0 && lane < 16) {
        int y = ws2[lane];
        #pragma unroll
        for (int off = 1; off < 16; off <<= 1) {
            int t = __shfl_up_sync(0xffffu, y, off);
            if (lane >= off) y += t;
        }
        ws2[lane] = y;
    }
    __syncthreads();
    if (b == 0 && tid < NG)
        g_gptr[tid] = x2 + (warp ? ws2[warp - 1] : 0) - gv;
    if (b == 0 && tid == 0) g_gptr[NG] = NN;

    __syncthreads();
    if (tid == 0) {
        int t = atomicAdd(&g_done, 1);
        if (t == NBLK - 1) {
            #pragma unroll 1
            for (int i = 0; i < NBLK; i++) g_desc[i] = 0;
            g_done = 0;
            __threadfence();
        }
    }
}

// ---------------- scatter (atomic-free) + xh *= dinv[row] scaling ------------
__global__ void k_scatter(const void* __restrict__ ei, const float* __restrict__ ew) {
    int i = blockIdx.x * blockDim.x + threadIdx.x;
    if (i >= NE) return;     // NE == NN*IND/2: same bound covers both jobs
    // job 1: place edge record (src u16 | ew fp16)
    int s, d;
    if (g_is64) {
        const long long* p = (const long long*)ei;
        s = (int)p[i]; d = (int)p[NE + i];
    } else {
        const int* p = (const int*)ei;
        s = p[i]; d = p[NE + i];
    }
    int pos = g_rowptr[d] + (int)g_rank[i];
    g_edge[pos] = (unsigned)s |
                  ((unsigned)__half_as_ushort(__float2half_rn(ew[i])) << 16);
    // job 2: scale x features by dinv[row] (i indexes half2; 32 per row)
    float dn = g_dinv[i >> 5];
    float2 v = __half22float2(((const __half2*)g_xh)[i]);
    ((__half2*)g_xh)[i] = __floats2half2_rn(v.x * dn, v.y * dn);
}

// ---------------- layer-1 aggregation: axh = fp16(S @ x), 64-dim -------------
// g_xh is pre-scaled by dinv[src]; out = dn * (edge_sum + xs[node])
__global__ void __launch_bounds__(256) k_aggx() {
    int node = (blockIdx.x * 256 + threadIdx.x) >> 5;
    int lane = threadIdx.x & 31;
    if (node >= NN) return;
    float dn = g_dinv[node];
    float2 self = __half22float2(((const __half2*)g_xh)[node * 32 + lane]);
    float2 acc = self;   // self term: dn * xs[node] = dn^2 * x[node]  ✓
    int e   = g_rowptr[node];
    int end = g_rowptr[node + 1];
    #pragma unroll 4
    for (; e < end; e++) {
        unsigned rec = __ldg(&g_edge[e]);
        int src  = rec & 0xFFFFu;
        float w  = __half2float(__ushort_as_half((unsigned short)(rec >> 16)));
        float2 hs = __half22float2(((const __half2*)g_xh)[src * 32 + lane]);
        acc.x += hs.x * w; acc.y += hs.y * w;
    }
    ((__half2*)g_axh)[node * 32 + lane] = __floats2half2_rn(acc.x * dn, acc.y * dn);
}

// ---------------- fused double GEMM: h2h = dinv .* ((relu(ax@W1+b1)) @ W2) ----
// 256 thr (8 warps: 4xM, 2xN), tile 128x128. Stage-1 result kept in smem (U).
__global__ void __launch_bounds__(256) k_gemmf(const float* __restrict__ bias) {
    constexpr int LDU = 136;           // halves (128+8 pad)
    constexpr int KC  = 32;
    __shared__ __half U[128 * LDU];    // 34.8 KB: stage-1 A, then a1 tile
    __shared__ __half Bs[KC * LDU];    //  8.7 KB: W chunks
    int tid = threadIdx.x;
    int row0 = blockIdx.x * 128;
    int warp = tid >> 5, lane = tid & 31;
    int wm = (warp & 3) * 32;
    int wn = (warp >> 2) * 64;
    float acc[2][8][4];

    #pragma unroll
    for (int mi = 0; mi < 2; mi++)
        #pragma unroll
        for (int nj = 0; nj < 8; nj++)
            #pragma unroll
            for (int q = 0; q < 4; q++) acc[mi][nj][q] = 0.f;

    // stage-1 A: g_axh rows (128 x 64 halves) into U cols [0,64)
    for (int i = tid; i < 128 * IND / 8; i += 256) {
        int r = i >> 3, c = (i & 7) * 8;
        uint4 v = make_uint4(0u, 0u, 0u, 0u);
        if (row0 + r < NN)
            v = ((const uint4*)g_axh)[(row0 + r) * (IND / 8) + c / 8];
        *(uint4*)&U[r * LDU + c] = v;
    }
    // stage 1: K=64 in two 32-chunks of W1
    #pragma unroll 1
    for (int kc = 0; kc < IND; kc += KC) {
        __syncthreads();
        for (int i = tid; i < KC * 128 / 8; i += 256) {
            int r = i >> 4, c = (i & 15) * 8;
            *(uint4*)&Bs[r * LDU + c] = ((const uint4*)g_w1h)[((kc + r) * 128 + c) / 8];
        }
        __syncthreads();
        #pragma unroll
        for (int k = 0; k < KC; k += 16) {
            uint32_t a[2][4], b[4][4];
            #pragma unroll
            for (int mi = 0; mi < 2; mi++) {
                uint32_t addr = (uint32_t)__cvta_generic_to_shared(
                    &U[(wm + mi * 16 + (lane & 15)) * LDU + kc + k + 8 * (lane >> 4)]);
                asm volatile("ldmatrix.sync.aligned.m8n8.x4.shared.b16 {%0,%1,%2,%3}, [%4];"
                             : "=r"(a[mi][0]), "=r"(a[mi][1]), "=r"(a[mi][2]), "=r"(a[mi][3])
                             : "r"(addr));
            }
            #pragma unroll
            for (int ni = 0; ni < 4; ni++) {
                uint32_t addr = (uint32_t)__cvta_generic_to_shared(
                    &Bs[(k + (lane & 15)) * LDU + wn + ni * 16 + 8 * (lane >> 4)]);
                asm volatile("ldmatrix.sync.aligned.m8n8.x4.trans.shared.b16 {%0,%1,%2,%3}, [%4];"
                             : "=r"(b[ni][0]), "=r"(b[ni][1]), "=r"(b[ni][2]), "=r"(b[ni][3])
                             : "r"(addr));
            }
            #pragma unroll
            for (int mi = 0; mi < 2; mi++)
                #pragma unroll
                for (int nj = 0; nj < 8; nj++) {
                    uint32_t b0 = b[nj >> 1][(nj & 1) * 2 + 0];
                    uint32_t b1 = b[nj >> 1][(nj & 1) * 2 + 1];
                    asm volatile(
                        "mma.sync.aligned.m16n8k16.row.col.f32.f16.f16.f32 "
                        "{%0,%1,%2,%3}, {%4,%5,%6,%7}, {%8,%9}, {%0,%1,%2,%3};"
                        : "+f"(acc[mi][nj][0]), "+f"(acc[mi][nj][1]),
                          "+f"(acc[mi][nj][2]), "+f"(acc[mi][nj][3])
                        : "r"(a[mi][0]), "r"(a[mi][1]), "r"(a[mi][2]), "r"(a[mi][3]),
                          "r"(b0), "r"(b1));
                }
        }
    }
    __syncthreads();   // all stage-1 reads of U complete
    // epilogue 1: bias + relu -> fp16 a1 tile back into U (full 128 cols)
    #pragma unroll
    for (int mi = 0; mi < 2; mi++)
        #pragma unroll
        for (int nj = 0; nj < 8; nj++) {
            int col = wn + nj * 8 + 2 * (lane & 3);
            float bx = bias[col], by = bias[col + 1];
            #pragma unroll
            for (int h = 0; h < 2; h++) {
                int r = wm + mi * 16 + (lane >> 2) + h * 8;
                float v0 = fmaxf(acc[mi][nj][2 * h + 0] + bx, 0.f);
                float v1 = fmaxf(acc[mi][nj][2 * h + 1] + by, 0.f);
                *(__half2*)&U[r * LDU + col] = __floats2half2_rn(v0, v1);
                acc[mi][nj][2 * h + 0] = 0.f;   // reset for stage 2
                acc[mi][nj][2 * h + 1] = 0.f;
            }
        }
    // stage 2: K=128 in four 32-chunks of W2, A = a1 tile in U
    #pragma unroll 1
    for (int kc = 0; kc < HID; kc += KC) {
        __syncthreads();
        for (int i = tid; i < KC * 128 / 8; i += 256) {
            int r = i >> 4, c = (i & 15) * 8;
            *(uint4*)&Bs[r * LDU + c] = ((const uint4*)g_w2h)[((kc + r) * 128 + c) / 8];
        }
        __syncthreads();
        #pragma unroll
        for (int k = 0; k < KC; k += 16) {
            uint32_t a[2][4], b[4][4];
            #pragma unroll
            for (int mi = 0; mi < 2; mi++) {
                uint32_t addr = (uint32_t)__cvta_generic_to_shared(
                    &U[(wm + mi * 16 + (lane & 15)) * LDU + kc + k + 8 * (lane >> 4)]);
                asm volatile("ldmatrix.sync.aligned.m8n8.x4.shared.b16 {%0,%1,%2,%3}, [%4];"
                             : "=r"(a[mi][0]), "=r"(a[mi][1]), "=r"(a[mi][2]), "=r"(a[mi][3])
                             : "r"(addr));
            }
            #pragma unroll
            for (int ni = 0; ni < 4; ni++) {
                uint32_t addr = (uint32_t)__cvta_generic_to_shared(
                    &Bs[(k + (lane & 15)) * LDU + wn + ni * 16 + 8 * (lane >> 4)]);
                asm volatile("ldmatrix.sync.aligned.m8n8.x4.trans.shared.b16 {%0,%1,%2,%3}, [%4];"
                             : "=r"(b[ni][0]), "=r"(b[ni][1]), "=r"(b[ni][2]), "=r"(b[ni][3])
                             : "r"(addr));
            }
            #pragma unroll
            for (int mi = 0; mi < 2; mi++)
                #pragma unroll
                for (int nj = 0; nj < 8; nj++) {
                    uint32_t b0 = b[nj >> 1][(nj & 1) * 2 + 0];
                    uint32_t b1 = b[nj >> 1][(nj & 1) * 2 + 1];
                    asm volatile(
                        "mma.sync.aligned.m16n8k16.row.col.f32.f16.f16.f32 "
                        "{%0,%1,%2,%3}, {%4,%5,%6,%7}, {%8,%9}, {%0,%1,%2,%3};"
                        : "+f"(acc[mi][nj][0]), "+f"(acc[mi][nj][1]),
                          "+f"(acc[mi][nj][2]), "+f"(acc[mi][nj][3])
                        : "r"(a[mi][0]), "r"(a[mi][1]), "r"(a[mi][2]), "r"(a[mi][3]),
                          "r"(b0), "r"(b1));
                }
        }
    }
    // epilogue 2: scale by dinv[row], store fp16 h2h
    #pragma unroll
    for (int mi = 0; mi < 2; mi++)
        #pragma unroll
        for (int nj = 0; nj < 8; nj++) {
            int col = wn + nj * 8 + 2 * (lane & 3);
            #pragma unroll
            for (int h = 0; h < 2; h++) {
                int r = row0 + wm + mi * 16 + (lane >> 2) + h * 8;
                if (r < NN) {
                    float dn = g_dinv[r];
                    float v0 = acc[mi][nj][2 * h + 0] * dn;
                    float v1 = acc[mi][nj][2 * h + 1] * dn;
                    ((__half2*)g_h2h)[(r * 128 + col) >> 1] = __floats2half2_rn(v0, v1);
                }
            }
        }
}

// ---------------- layer-2 aggregation: a2h = fp16(relu(S @ h2 + b2)) ---------
// g_h2h is pre-scaled by dinv[row]; out = relu(dn*(edge_sum + h2s[node]) + b2)
__global__ void __launch_bounds__(256) k_agg128(const float* __restrict__ bias) {
    int node = (blockIdx.x * 256 + threadIdx.x) >> 5;
    int lane = threadIdx.x & 31;
    if (node >= NN) return;
    float dn = g_dinv[node];
    uint2 sv = ((const uint2*)g_h2h)[node * 32 + lane];
    float2 s0 = __half22float2(*(__half2*)&sv.x);
    float2 s1 = __half22float2(*(__half2*)&sv.y);
    float4 acc = make_float4(s0.x, s0.y, s1.x, s1.y);
    int e   = g_rowptr[node];
    int end = g_rowptr[node + 1];
    #pragma unroll 4
    for (; e < end; e++) {
        unsigned rec = __ldg(&g_edge[e]);
        int src  = rec & 0xFFFFu;
        float w  = __half2float(__ushort_as_half((unsigned short)(rec >> 16)));
        uint2 hv = ((const uint2*)g_h2h)[src * 32 + lane];
        float2 f0 = __half22float2(*(__half2*)&hv.x);
        float2 f1 = __half22float2(*(__half2*)&hv.y);
        acc.x += f0.x * w; acc.y += f0.y * w;
        acc.z += f1.x * w; acc.w += f1.y * w;
    }
    float4 b = ((const float4*)bias)[lane];
    acc.x = fmaxf(acc.x * dn + b.x, 0.f);
    acc.y = fmaxf(acc.y * dn + b.y, 0.f);
    acc.z = fmaxf(acc.z * dn + b.z, 0.f);
    acc.w = fmaxf(acc.w * dn + b.w, 0.f);
    uint2 pk;
    __half2 h0 = __floats2half2_rn(acc.x, acc.y);
    __half2 h1 = __floats2half2_rn(acc.z, acc.w);
    pk.x = *(unsigned*)&h0;
    pk.y = *(unsigned*)&h1;
    ((uint2*)g_a2h)[node * 32 + lane] = pk;
}

// ---------------- fused pool (sorted batch -> contiguous ranges) + MLP head --
__global__ void __launch_bounds__(128) k_poolmlp(const float* __restrict__ Wm1,
                                                 const float* __restrict__ bm1,
                                                 const float* __restrict__ Wm2,
                                                 const float* __restrict__ bm2,
                                                 float* __restrict__ out) {
    int g = blockIdx.x;
    int tid = threadIdx.x;
    __shared__ float ps[HID];
    __shared__ float zs[HID];
    int n0 = g_gptr[g], n1 = g_gptr[g + 1];
    float acc = 0.f;
    for (int n = n0; n < n1; n++)
        acc += __half2float(g_a2h[n * HID + tid]);
    ps[tid] = acc;
    __syncthreads();
    float z = bm1[tid];
    #pragma unroll 8
    for (int k = 0; k < HID; k++) z += ps[k] * Wm1[k * HID + tid];
    zs[tid] = fmaxf(z, 0.f);
    __syncthreads();
    if (tid < OUTD) {
        float a = bm2[tid];
        #pragma unroll 8
        for (int k = 0; k < HID; k++) a += zs[k] * Wm2[k * OUTD + tid];
        out[g * OUTD + tid] = a;
    }
}

// ---------------- launch ----------------
extern "C" void kernel_launch(void* const* d_in, const int* in_sizes, int n_in,
                              void* d_out, int out_size) {
    const float* x   = (const float*)d_in[0];
    const void*  ei  = d_in[1];
    const void*  bt  = d_in[2];
    const float* ew  = (const float*)d_in[3];
    const float* W1  = (const float*)d_in[4];
    const float* b1  = (const float*)d_in[5];
    const float* W2  = (const float*)d_in[6];
    const float* b2  = (const float*)d_in[7];
    const float* Wm1 = (const float*)d_in[8];
    const float* bm1 = (const float*)d_in[9];
    const float* Wm2 = (const float*)d_in[10];
    const float* bm2 = (const float*)d_in[11];
    float* out = (float*)d_out;

    k_detect<<<1, 128>>>((const unsigned*)ei);
    k_histpre<<<(NE + 255) / 256, 256>>>(ei, bt, ew, x, W1, W2);
    k_scan<<<NBLK, SCAN_B>>>();
    k_scatter<<<(NE + 255) / 256, 256>>>(ei, ew);
    k_aggx<<<(NN * 32 + 255) / 256, 256>>>();
    k_gemmf<<<(NN + 127) / 128, 256>>>(b1);
    k_agg128<<<(NN * 32 + 255) / 256, 256>>>(b2);
    k_poolmlp<<<NG, 128>>>(Wm1, bm1, Wm2, bm2, out);
}